// round 1
// baseline (speedup 1.0000x reference)
#include <cuda_runtime.h>

// ---------------- scratch (allocation-free) ----------------
__device__ float g_q [4096 * 1024];   // scaled Q:  [B*QN,  H*Dh]
__device__ float g_k [2048 * 1024];   // K:         [B*NDS, H*Dh]
__device__ float g_v [2048 * 1024];   // V:         [B*NDS, H*Dh]
__device__ float g_ao[4096 * 1024];   // attn out:  [B*QN,  H*Dh]

// ---------------- fast exp2 on the FMA pipe ----------------
// valid for x <= 0 (clamped at -120); relative error ~2.4e-6
__device__ __forceinline__ float fexp2(float x) {
    x = fmaxf(x, -120.0f);
    float t = x + 12582912.0f;          // 1.5*2^23 : round(x) lands in mantissa
    float f = x - (t - 12582912.0f);    // f in [-0.5, 0.5], exact
    int   e = __float_as_int(t) << 23;  // round(x) shifted into exponent field
    float p = 1.33335581e-3f;
    p = fmaf(p, f, 9.61812911e-3f);
    p = fmaf(p, f, 5.55041087e-2f);
    p = fmaf(p, f, 2.40226507e-1f);
    p = fmaf(p, f, 6.93147181e-1f);
    p = fmaf(p, f, 1.0f);
    return __int_as_float(__float_as_int(p) + e);
}

// ---------------- 128x128x8 fp32 GEMM, 8x8 micro-tiles ----------------
// C[M,N] = alpha * (A[M,K] @ B[K,N]) + bias   (row-major; M%128==N%128==K%8==0)
__global__ __launch_bounds__(256)
void sgemm_kernel(const float* __restrict__ A, const float* __restrict__ B,
                  const float* __restrict__ bias, float* __restrict__ C,
                  int M, int N, int K, float alpha) {
    __shared__ float As[8][128];
    __shared__ float Bs[8][128];

    const int tid = threadIdx.x;
    const int tx  = tid & 15;
    const int ty  = tid >> 4;
    const int bx  = blockIdx.x;   // N tile
    const int by  = blockIdx.y;   // M tile

    const int aRow = tid >> 1;            // 0..127
    const int aCol = (tid & 1) * 4;       // 0 or 4
    const int bRow = tid >> 5;            // 0..7
    const int bCol = (tid & 31) * 4;      // 0..124

    const float* Ag = A + (by * 128 + aRow) * K + aCol;
    const float* Bg = B + bRow * N + bx * 128 + bCol;

    float acc[8][8];
#pragma unroll
    for (int i = 0; i < 8; i++)
#pragma unroll
        for (int j = 0; j < 8; j++) acc[i][j] = 0.0f;

    for (int k0 = 0; k0 < K; k0 += 8) {
        float4 a4 = *(const float4*)(Ag + k0);
        As[aCol + 0][aRow] = a4.x;
        As[aCol + 1][aRow] = a4.y;
        As[aCol + 2][aRow] = a4.z;
        As[aCol + 3][aRow] = a4.w;
        *(float4*)&Bs[bRow][bCol] = *(const float4*)(Bg + k0 * N);
        __syncthreads();
#pragma unroll
        for (int kk = 0; kk < 8; kk++) {
            float ar[8], br[8];
            *(float4*)(ar)     = *(const float4*)&As[kk][ty * 8];
            *(float4*)(ar + 4) = *(const float4*)&As[kk][ty * 8 + 4];
            *(float4*)(br)     = *(const float4*)&Bs[kk][tx * 8];
            *(float4*)(br + 4) = *(const float4*)&Bs[kk][tx * 8 + 4];
#pragma unroll
            for (int i = 0; i < 8; i++)
#pragma unroll
                for (int j = 0; j < 8; j++)
                    acc[i][j] = fmaf(ar[i], br[j], acc[i][j]);
        }
        __syncthreads();
    }

#pragma unroll
    for (int i = 0; i < 8; i++) {
        int row = by * 128 + ty * 8 + i;
        float* Cp = C + row * N + bx * 128 + tx * 8;
#pragma unroll
        for (int jj = 0; jj < 2; jj++) {
            float4 r;
            r.x = alpha * acc[i][jj * 4 + 0];
            r.y = alpha * acc[i][jj * 4 + 1];
            r.z = alpha * acc[i][jj * 4 + 2];
            r.w = alpha * acc[i][jj * 4 + 3];
            if (bias) {
                const float* bp = bias + bx * 128 + tx * 8 + jj * 4;
                r.x += bp[0]; r.y += bp[1]; r.z += bp[2]; r.w += bp[3];
            }
            *(float4*)(Cp + jj * 4) = r;
        }
    }
}

// ---------------- fused banded attention over 1024 unique keys ----------------
// grid: (QN/128, HEADS, B), block: 256
// per block: 128 q-rows of one head; streams 64-key blocks, online softmax,
// multiplicity m(u,i) = [u >= i-2] + [u >= i-1026] handles the tiled-KV duplication.
#define ATS 68     // padded row stride for Kt/Vs/Ps (floats)
#define QTS 132    // padded row stride for Qt (floats)
#define ATTN_SMEM ((64 * QTS + 64 * ATS + 64 * ATS + 128 * ATS) * 4)

__global__ __launch_bounds__(256, 2)
void attn_kernel(const float* __restrict__ q, const float* __restrict__ k,
                 const float* __restrict__ v, float* __restrict__ o) {
    extern __shared__ float sm[];
    float* Qt = sm;                     // [64][QTS]  Qt[d][r]
    float* Kt = Qt + 64 * QTS;          // [64][ATS]  Kt[d][c]
    float* Vs = Kt + 64 * ATS;          // [64][ATS]  Vs[u][e]
    float* Ps = Vs + 64 * ATS;          // [128][ATS] Ps[r][c]

    const int qt  = blockIdx.x;
    const int h   = blockIdx.y;
    const int b   = blockIdx.z;
    const int qi0 = qt * 128;
    const int tid = threadIdx.x;
    const int tx  = tid & 15;
    const int ty  = tid >> 4;
    const int r0  = ty * 8;             // 8 query rows per thread
    const int c0  = tx * 4;             // 4 key cols / 4 out dims per thread

    // --- load Q tile transposed (conflict-free smem writes) ---
    const float* qg = q + (b * 2048 + qi0) * 1024 + h * 64;
    for (int t = tid; t < 128 * 16; t += 256) {
        int r  = t & 127;
        int d4 = (t >> 7) << 2;
        float4 val = *(const float4*)(qg + r * 1024 + d4);
        Qt[(d4 + 0) * QTS + r] = val.x;
        Qt[(d4 + 1) * QTS + r] = val.y;
        Qt[(d4 + 2) * QTS + r] = val.z;
        Qt[(d4 + 3) * QTS + r] = val.w;
    }

    float m[8], l[8], oacc[8][4];
#pragma unroll
    for (int i = 0; i < 8; i++) {
        m[i] = -1e30f; l[i] = 0.0f;
#pragma unroll
        for (int j = 0; j < 4; j++) oacc[i][j] = 0.0f;
    }
    __syncthreads();

    const float* kg = k + b * 1024 * 1024 + h * 64;
    const float* vg = v + b * 1024 * 1024 + h * 64;

    for (int u0 = 0; u0 < 1024; u0 += 64) {
        if (u0 + 63 < qi0 - 1026) continue;   // fully masked key block (uniform)

        // K transposed (conflict-free writes, L2-resident scattered reads)
        for (int t = tid; t < 64 * 16; t += 256) {
            int c  = t & 63;
            int d4 = (t >> 6) << 2;
            float4 val = *(const float4*)(kg + (u0 + c) * 1024 + d4);
            Kt[(d4 + 0) * ATS + c] = val.x;
            Kt[(d4 + 1) * ATS + c] = val.y;
            Kt[(d4 + 2) * ATS + c] = val.z;
            Kt[(d4 + 3) * ATS + c] = val.w;
        }
        // V natural (fully coalesced)
        for (int t = tid; t < 64 * 16; t += 256) {
            int u  = t >> 4;
            int d4 = (t & 15) << 2;
            *(float4*)(Vs + u * ATS + d4) = *(const float4*)(vg + (u0 + u) * 1024 + d4);
        }
        __syncthreads();

        // --- S = Qs * K^T (s already carries scale*log2e from the Q projection) ---
        float sacc[8][4];
#pragma unroll
        for (int i = 0; i < 8; i++)
#pragma unroll
            for (int j = 0; j < 4; j++) sacc[i][j] = 0.0f;

#pragma unroll 4
        for (int d = 0; d < 64; d++) {
            float ar[8], br[4];
            *(float4*)(ar)     = *(const float4*)(Qt + d * QTS + r0);
            *(float4*)(ar + 4) = *(const float4*)(Qt + d * QTS + r0 + 4);
            *(float4*)(br)     = *(const float4*)(Kt + d * ATS + c0);
#pragma unroll
            for (int i = 0; i < 8; i++)
#pragma unroll
                for (int j = 0; j < 4; j++)
                    sacc[i][j] = fmaf(ar[i], br[j], sacc[i][j]);
        }

        // --- online softmax update ---
#pragma unroll
        for (int i = 0; i < 8; i++) {
            const int ig = qi0 + r0 + i;
            float mf[4];
            float rmax = -1e30f;
#pragma unroll
            for (int j = 0; j < 4; j++) {
                int u = u0 + c0 + j;
                float f = (u >= ig - 2 ? 1.0f : 0.0f) + (u >= ig - 1026 ? 1.0f : 0.0f);
                mf[j] = f;
                if (f == 0.0f) sacc[i][j] = -1e30f;
                rmax = fmaxf(rmax, sacc[i][j]);
            }
#pragma unroll
            for (int w = 1; w < 16; w <<= 1)
                rmax = fmaxf(rmax, __shfl_xor_sync(0xffffffffu, rmax, w));
            float mn    = fmaxf(m[i], rmax);
            float scale = fexp2(m[i] - mn);
            m[i] = mn;

            float p0 = mf[0] * fexp2(sacc[i][0] - mn);
            float p1 = mf[1] * fexp2(sacc[i][1] - mn);
            float p2 = mf[2] * fexp2(sacc[i][2] - mn);
            float p3 = mf[3] * fexp2(sacc[i][3] - mn);
            *(float4*)(Ps + (r0 + i) * ATS + c0) = make_float4(p0, p1, p2, p3);

            float rsum = p0 + p1 + p2 + p3;
#pragma unroll
            for (int w = 1; w < 16; w <<= 1)
                rsum += __shfl_xor_sync(0xffffffffu, rsum, w);
            l[i] = l[i] * scale + rsum;
#pragma unroll
            for (int j = 0; j < 4; j++) oacc[i][j] *= scale;
        }
        __syncthreads();   // Ps visible to all

        // --- O += P @ V ---
#pragma unroll 4
        for (int u = 0; u < 64; u++) {
            float br[4];
            *(float4*)(br) = *(const float4*)(Vs + u * ATS + c0);
#pragma unroll
            for (int i = 0; i < 8; i++) {
                float a = Ps[(r0 + i) * ATS + u];
#pragma unroll
                for (int j = 0; j < 4; j++)
                    oacc[i][j] = fmaf(a, br[j], oacc[i][j]);
            }
        }
        __syncthreads();   // protect Kt/Vs/Ps before next block's loads
    }

    // --- normalize and write [B, QN, H*Dh] ---
    float* og = o + (b * 2048 + qi0) * 1024 + h * 64;
#pragma unroll
    for (int i = 0; i < 8; i++) {
        float inv = 1.0f / l[i];
        float4 r = make_float4(oacc[i][0] * inv, oacc[i][1] * inv,
                               oacc[i][2] * inv, oacc[i][3] * inv);
        *(float4*)(og + (r0 + i) * 1024 + c0) = r;
    }
}

// ---------------- launch ----------------
extern "C" void kernel_launch(void* const* d_in, const int* in_sizes, int n_in,
                              void* d_out, int out_size) {
    const float* x  = (const float*)d_in[0];  // unet_full        [2,2048,1024]
    const float* xd = (const float*)d_in[1];  // unet_downsampled [2,1024,1024]
    const float* Wq = (const float*)d_in[2];
    const float* Wk = (const float*)d_in[3];
    const float* Wv = (const float*)d_in[4];
    const float* Wo = (const float*)d_in[5];
    const float* bo = (const float*)d_in[6];
    float* out = (float*)d_out;               // [2,2048,1024]

    float *gq, *gk, *gv, *gao;
    cudaGetSymbolAddress((void**)&gq,  g_q);
    cudaGetSymbolAddress((void**)&gk,  g_k);
    cudaGetSymbolAddress((void**)&gv,  g_v);
    cudaGetSymbolAddress((void**)&gao, g_ao);

    cudaFuncSetAttribute(attn_kernel, cudaFuncAttributeMaxDynamicSharedMemorySize,
                         ATTN_SMEM);

    // fold softmax scale AND log2(e) into Q so attention uses exp2 directly
    const float qscale = 0.125f * 1.44269504088896341f;

    dim3 blk(256);
    sgemm_kernel<<<dim3(8, 32), blk>>>(x,  Wq, nullptr, gq, 4096, 1024, 1024, qscale);
    sgemm_kernel<<<dim3(8, 16), blk>>>(xd, Wk, nullptr, gk, 2048, 1024, 1024, 1.0f);
    sgemm_kernel<<<dim3(8, 16), blk>>>(xd, Wv, nullptr, gv, 2048, 1024, 1024, 1.0f);

    attn_kernel<<<dim3(16, 16, 2), blk, ATTN_SMEM>>>(gq, gk, gv, gao);

    sgemm_kernel<<<dim3(8, 32), blk>>>(gao, Wo, bo, out, 4096, 1024, 1024, 1.0f);
}

// round 3
// speedup vs baseline: 1.6810x; 1.6810x over previous
#include <cuda_runtime.h>
#include <cuda_bf16.h>
#include <cstdint>

// ============================ scratch (allocation-free) ============================
__device__ float g_q [4096 * 1024];
__device__ float g_k [2048 * 1024];
__device__ float g_v [2048 * 1024];
__device__ float g_ao[4096 * 1024];

__device__ __nv_bfloat16 g_xh [4096 * 1024];
__device__ __nv_bfloat16 g_xl [4096 * 1024];
__device__ __nv_bfloat16 g_dh [2048 * 1024];
__device__ __nv_bfloat16 g_dl [2048 * 1024];
__device__ __nv_bfloat16 g_aoh[4096 * 1024];
__device__ __nv_bfloat16 g_aol[4096 * 1024];
__device__ __nv_bfloat16 g_wqh[1024 * 1024], g_wql[1024 * 1024];
__device__ __nv_bfloat16 g_wkh[1024 * 1024], g_wkl[1024 * 1024];
__device__ __nv_bfloat16 g_wvh[1024 * 1024], g_wvl[1024 * 1024];
__device__ __nv_bfloat16 g_woh[1024 * 1024], g_wol[1024 * 1024];

// ============================ PTX helpers (arch-generic) ============================
__device__ __forceinline__ uint32_t smem_u32(const void* p) {
    uint32_t a;
    asm("{ .reg .u64 t; cvta.to.shared.u64 t, %1; cvt.u32.u64 %0, t; }" : "=r"(a) : "l"(p));
    return a;
}
__device__ __forceinline__ void ldsm_x4(uint32_t& r0, uint32_t& r1, uint32_t& r2, uint32_t& r3,
                                        uint32_t addr) {
    asm volatile("ldmatrix.sync.aligned.m8n8.x4.shared.b16 {%0,%1,%2,%3}, [%4];"
                 : "=r"(r0), "=r"(r1), "=r"(r2), "=r"(r3) : "r"(addr));
}
__device__ __forceinline__ void mma_bf16(float* d, const uint32_t* a, uint32_t b0, uint32_t b1) {
    asm volatile("mma.sync.aligned.m16n8k16.row.col.f32.bf16.bf16.f32 "
                 "{%0,%1,%2,%3}, {%4,%5,%6,%7}, {%8,%9}, {%0,%1,%2,%3};"
                 : "+f"(d[0]), "+f"(d[1]), "+f"(d[2]), "+f"(d[3])
                 : "r"(a[0]), "r"(a[1]), "r"(a[2]), "r"(a[3]), "r"(b0), "r"(b1));
}
__device__ __forceinline__ void cp_async16(uint32_t dst, const void* src) {
    asm volatile("cp.async.cg.shared.global [%0], [%1], 16;" :: "r"(dst), "l"(src) : "memory");
}
__device__ __forceinline__ void cp_commit() {
    asm volatile("cp.async.commit_group;" ::: "memory");
}

// ============================ split / transpose conversions ============================
__global__ void split_bf16_kernel(const float* __restrict__ in,
                                  __nv_bfloat16* __restrict__ hi,
                                  __nv_bfloat16* __restrict__ lo, int n4) {
    int i = blockIdx.x * blockDim.x + threadIdx.x;
    if (i >= n4) return;
    float4 v = ((const float4*)in)[i];
    __nv_bfloat16 h0 = __float2bfloat16(v.x), h1 = __float2bfloat16(v.y);
    __nv_bfloat16 h2 = __float2bfloat16(v.z), h3 = __float2bfloat16(v.w);
    __nv_bfloat16 l0 = __float2bfloat16(v.x - __bfloat162float(h0));
    __nv_bfloat16 l1 = __float2bfloat16(v.y - __bfloat162float(h1));
    __nv_bfloat16 l2 = __float2bfloat16(v.z - __bfloat162float(h2));
    __nv_bfloat16 l3 = __float2bfloat16(v.w - __bfloat162float(h3));
    ((__nv_bfloat162*)hi)[2 * i + 0] = __nv_bfloat162(h0, h1);
    ((__nv_bfloat162*)hi)[2 * i + 1] = __nv_bfloat162(h2, h3);
    ((__nv_bfloat162*)lo)[2 * i + 0] = __nv_bfloat162(l0, l1);
    ((__nv_bfloat162*)lo)[2 * i + 1] = __nv_bfloat162(l2, l3);
}

// W [1024 k][1024 n] row-major  ->  Wt_hi/lo [n][k] bf16
__global__ void wsplit_transpose_kernel(const float* __restrict__ W,
                                        __nv_bfloat16* __restrict__ th,
                                        __nv_bfloat16* __restrict__ tl) {
    __shared__ float t[32][33];
    int x = blockIdx.x * 32 + threadIdx.x;   // n
#pragma unroll
    for (int j = 0; j < 32; j += 8) {
        int kk = blockIdx.y * 32 + threadIdx.y + j;
        t[threadIdx.y + j][threadIdx.x] = W[kk * 1024 + x];
    }
    __syncthreads();
    int kx = blockIdx.y * 32 + threadIdx.x;  // k
#pragma unroll
    for (int j = 0; j < 32; j += 8) {
        int n = blockIdx.x * 32 + threadIdx.y + j;
        float v = t[threadIdx.x][threadIdx.y + j];
        __nv_bfloat16 h = __float2bfloat16(v);
        __nv_bfloat16 l = __float2bfloat16(v - __bfloat162float(h));
        th[n * 1024 + kx] = h;
        tl[n * 1024 + kx] = l;
    }
}

// ============================ mma.sync compensated-bf16 GEMM ============================
// C[M,1024] = alpha * A[M,1024] @ W[1024,1024] (+ bias)
// 3-term: AhBh + AhBl + AlBh  (Bt stored [N][K] row-major = col-major B for mma)
// grid (8, M/128), block 256 (8 warps, 4x2), 2-stage cp.async pipeline.
#define GTS      72                      // smem tile row stride in bf16 (144B: conflict-free)
#define GTILE_B  (128 * GTS * 2)         // 18432 B per tile
#define G_SMEM   (8 * GTILE_B)           // 2 stages x 4 tiles = 147456 B

__global__ __launch_bounds__(256, 1)
void gemm_mma_kernel(const __nv_bfloat16* __restrict__ Ah,
                     const __nv_bfloat16* __restrict__ Al,
                     const __nv_bfloat16* __restrict__ Bh,
                     const __nv_bfloat16* __restrict__ Bl,
                     const float* __restrict__ bias,
                     float* __restrict__ C, float alpha) {
    extern __shared__ char smem[];
    const uint32_t sbase = smem_u32(smem);
    const int tid  = threadIdx.x;
    const int lane = tid & 31;
    const int wid  = tid >> 5;
    const int wm   = wid & 3;            // warp row (4)
    const int wn   = wid >> 2;           // warp col (2)
    const int m0   = blockIdx.y * 128;
    const int n0   = blockIdx.x * 128;

    // ---- issue cp.async loads for chunk c into stage s ----
    // part p: 0=Ah 1=Al 2=Bh 3=Bl; each part 128 rows x 64 k (8x 16B per row)
    auto issue_loads = [&](int c, int s) {
#pragma unroll
        for (int it = 0; it < 16; it++) {
            const int part = it >> 2;                    // compile-time after unroll
            const int w    = tid + (it & 3) * 256;       // 0..1023
            const int row  = w >> 3;
            const int q    = w & 7;
            const __nv_bfloat16* base =
                (part == 0) ? Ah : (part == 1) ? Al : (part == 2) ? Bh : Bl;
            const int grow = (part < 2) ? (m0 + row) : (n0 + row);
            const void* src = base + ((size_t)grow << 10) + c * 64 + q * 8;
            uint32_t dst = sbase + (uint32_t)((s * 4 + part) * GTILE_B)
                         + (uint32_t)((row * GTS + q * 8) * 2);
            cp_async16(dst, src);
        }
        cp_commit();
    };

    float d[2][8][4];
#pragma unroll
    for (int mt = 0; mt < 2; mt++)
#pragma unroll
        for (int nt = 0; nt < 8; nt++)
#pragma unroll
            for (int e = 0; e < 4; e++) d[mt][nt][e] = 0.0f;

    issue_loads(0, 0);
    issue_loads(1, 1);

    for (int c = 0; c < 16; c++) {
        const int s = c & 1;
        asm volatile("cp.async.wait_group 1;" ::: "memory");
        __syncthreads();

        const uint32_t stage = sbase + (uint32_t)(s * 4 * GTILE_B);
#pragma unroll
        for (int pr = 0; pr < 3; pr++) {
            const int ap = (pr == 2) ? 1 : 0;            // Ah,Ah,Al
            const int bp = (pr == 1) ? 3 : 2;            // Bh,Bl,Bh
            const uint32_t abase = stage + (uint32_t)(ap * GTILE_B);
            const uint32_t bbase = stage + (uint32_t)(bp * GTILE_B);
#pragma unroll
            for (int ks = 0; ks < 4; ks++) {
                const int k16 = ks * 16;
                uint32_t af[2][4];
#pragma unroll
                for (int mt = 0; mt < 2; mt++) {
                    uint32_t addr = abase +
                        (uint32_t)(((wm * 32 + mt * 16 + (lane & 15)) * GTS
                                    + k16 + ((lane >> 4) * 8)) * 2);
                    ldsm_x4(af[mt][0], af[mt][1], af[mt][2], af[mt][3], addr);
                }
                uint32_t bf[4][4];
#pragma unroll
                for (int g = 0; g < 4; g++) {
                    const int mrow = lane >> 3;          // which 8x8 matrix
                    uint32_t addr = bbase +
                        (uint32_t)(((wn * 64 + g * 16 + (mrow & 2) * 4 + (lane & 7)) * GTS
                                    + k16 + ((mrow & 1) * 8)) * 2);
                    ldsm_x4(bf[g][0], bf[g][1], bf[g][2], bf[g][3], addr);
                }
#pragma unroll
                for (int mt = 0; mt < 2; mt++)
#pragma unroll
                    for (int nt = 0; nt < 8; nt++)
                        mma_bf16(d[mt][nt], af[mt],
                                 bf[nt >> 1][(nt & 1) * 2], bf[nt >> 1][(nt & 1) * 2 + 1]);
            }
        }
        __syncthreads();
        if (c + 2 < 16) issue_loads(c + 2, s);
        else            cp_commit();                     // keep group count consistent
    }

    // ---- epilogue ----
#pragma unroll
    for (int mt = 0; mt < 2; mt++) {
        const int row0 = m0 + wm * 32 + mt * 16 + (lane >> 2);
#pragma unroll
        for (int nt = 0; nt < 8; nt++) {
            const int col = n0 + wn * 64 + nt * 8 + (lane & 3) * 2;
            float bx = 0.0f, by = 0.0f;
            if (bias) { bx = bias[col]; by = bias[col + 1]; }
            float2 v0 = make_float2(d[mt][nt][0] * alpha + bx, d[mt][nt][1] * alpha + by);
            float2 v1 = make_float2(d[mt][nt][2] * alpha + bx, d[mt][nt][3] * alpha + by);
            *(float2*)(C + (size_t)row0 * 1024 + col)       = v0;
            *(float2*)(C + (size_t)(row0 + 8) * 1024 + col) = v1;
        }
    }
}

// ============================ fast exp2 on the FMA pipe ============================
__device__ __forceinline__ float fexp2(float x) {
    x = fmaxf(x, -120.0f);
    float t = x + 12582912.0f;
    float f = x - (t - 12582912.0f);
    int   e = __float_as_int(t) << 23;
    float p = 1.33335581e-3f;
    p = fmaf(p, f, 9.61812911e-3f);
    p = fmaf(p, f, 5.55041087e-2f);
    p = fmaf(p, f, 2.40226507e-1f);
    p = fmaf(p, f, 6.93147181e-1f);
    p = fmaf(p, f, 1.0f);
    return __int_as_float(__float_as_int(p) + e);
}

// ============================ fused banded attention (unchanged) ============================
#define ATS 68
#define QTS 132
#define ATTN_SMEM ((64 * QTS + 64 * ATS + 64 * ATS + 128 * ATS) * 4)

__global__ __launch_bounds__(256, 2)
void attn_kernel(const float* __restrict__ q, const float* __restrict__ k,
                 const float* __restrict__ v, float* __restrict__ o) {
    extern __shared__ float sm[];
    float* Qt = sm;
    float* Kt = Qt + 64 * QTS;
    float* Vs = Kt + 64 * ATS;
    float* Ps = Vs + 64 * ATS;

    const int qt  = blockIdx.x;
    const int h   = blockIdx.y;
    const int b   = blockIdx.z;
    const int qi0 = qt * 128;
    const int tid = threadIdx.x;
    const int tx  = tid & 15;
    const int ty  = tid >> 4;
    const int r0  = ty * 8;
    const int c0  = tx * 4;

    const float* qg = q + (b * 2048 + qi0) * 1024 + h * 64;
    for (int t = tid; t < 128 * 16; t += 256) {
        int r  = t & 127;
        int d4 = (t >> 7) << 2;
        float4 val = *(const float4*)(qg + r * 1024 + d4);
        Qt[(d4 + 0) * QTS + r] = val.x;
        Qt[(d4 + 1) * QTS + r] = val.y;
        Qt[(d4 + 2) * QTS + r] = val.z;
        Qt[(d4 + 3) * QTS + r] = val.w;
    }

    float m[8], l[8], oacc[8][4];
#pragma unroll
    for (int i = 0; i < 8; i++) {
        m[i] = -1e30f; l[i] = 0.0f;
#pragma unroll
        for (int j = 0; j < 4; j++) oacc[i][j] = 0.0f;
    }
    __syncthreads();

    const float* kg = k + b * 1024 * 1024 + h * 64;
    const float* vg = v + b * 1024 * 1024 + h * 64;

    for (int u0 = 0; u0 < 1024; u0 += 64) {
        if (u0 + 63 < qi0 - 1026) continue;

        for (int t = tid; t < 64 * 16; t += 256) {
            int c  = t & 63;
            int d4 = (t >> 6) << 2;
            float4 val = *(const float4*)(kg + (u0 + c) * 1024 + d4);
            Kt[(d4 + 0) * ATS + c] = val.x;
            Kt[(d4 + 1) * ATS + c] = val.y;
            Kt[(d4 + 2) * ATS + c] = val.z;
            Kt[(d4 + 3) * ATS + c] = val.w;
        }
        for (int t = tid; t < 64 * 16; t += 256) {
            int u  = t >> 4;
            int d4 = (t & 15) << 2;
            *(float4*)(Vs + u * ATS + d4) = *(const float4*)(vg + (u0 + u) * 1024 + d4);
        }
        __syncthreads();

        float sacc[8][4];
#pragma unroll
        for (int i = 0; i < 8; i++)
#pragma unroll
            for (int j = 0; j < 4; j++) sacc[i][j] = 0.0f;

#pragma unroll 4
        for (int d = 0; d < 64; d++) {
            float ar[8], br[4];
            *(float4*)(ar)     = *(const float4*)(Qt + d * QTS + r0);
            *(float4*)(ar + 4) = *(const float4*)(Qt + d * QTS + r0 + 4);
            *(float4*)(br)     = *(const float4*)(Kt + d * ATS + c0);
#pragma unroll
            for (int i = 0; i < 8; i++)
#pragma unroll
                for (int j = 0; j < 4; j++)
                    sacc[i][j] = fmaf(ar[i], br[j], sacc[i][j]);
        }

#pragma unroll
        for (int i = 0; i < 8; i++) {
            const int ig = qi0 + r0 + i;
            float mf[4];
            float rmax = -1e30f;
#pragma unroll
            for (int j = 0; j < 4; j++) {
                int u = u0 + c0 + j;
                float f = (u >= ig - 2 ? 1.0f : 0.0f) + (u >= ig - 1026 ? 1.0f : 0.0f);
                mf[j] = f;
                if (f == 0.0f) sacc[i][j] = -1e30f;
                rmax = fmaxf(rmax, sacc[i][j]);
            }
#pragma unroll
            for (int w = 1; w < 16; w <<= 1)
                rmax = fmaxf(rmax, __shfl_xor_sync(0xffffffffu, rmax, w));
            float mn    = fmaxf(m[i], rmax);
            float scale = fexp2(m[i] - mn);
            m[i] = mn;

            float p0 = mf[0] * fexp2(sacc[i][0] - mn);
            float p1 = mf[1] * fexp2(sacc[i][1] - mn);
            float p2 = mf[2] * fexp2(sacc[i][2] - mn);
            float p3 = mf[3] * fexp2(sacc[i][3] - mn);
            *(float4*)(Ps + (r0 + i) * ATS + c0) = make_float4(p0, p1, p2, p3);

            float rsum = p0 + p1 + p2 + p3;
#pragma unroll
            for (int w = 1; w < 16; w <<= 1)
                rsum += __shfl_xor_sync(0xffffffffu, rsum, w);
            l[i] = l[i] * scale + rsum;
#pragma unroll
            for (int j = 0; j < 4; j++) oacc[i][j] *= scale;
        }
        __syncthreads();

#pragma unroll 4
        for (int u = 0; u < 64; u++) {
            float br[4];
            *(float4*)(br) = *(const float4*)(Vs + u * ATS + c0);
#pragma unroll
            for (int i = 0; i < 8; i++) {
                float a = Ps[(r0 + i) * ATS + u];
#pragma unroll
                for (int j = 0; j < 4; j++)
                    oacc[i][j] = fmaf(a, br[j], oacc[i][j]);
            }
        }
        __syncthreads();
    }

    float* og = o + (b * 2048 + qi0) * 1024 + h * 64;
#pragma unroll
    for (int i = 0; i < 8; i++) {
        float inv = 1.0f / l[i];
        float4 r = make_float4(oacc[i][0] * inv, oacc[i][1] * inv,
                               oacc[i][2] * inv, oacc[i][3] * inv);
        *(float4*)(og + (r0 + i) * 1024 + c0) = r;
    }
}

// ============================ launch ============================
extern "C" void kernel_launch(void* const* d_in, const int* in_sizes, int n_in,
                              void* d_out, int out_size) {
    const float* x  = (const float*)d_in[0];
    const float* xd = (const float*)d_in[1];
    const float* Wq = (const float*)d_in[2];
    const float* Wk = (const float*)d_in[3];
    const float* Wv = (const float*)d_in[4];
    const float* Wo = (const float*)d_in[5];
    const float* bo = (const float*)d_in[6];
    float* out = (float*)d_out;

    float *gq, *gk, *gv, *gao;
    cudaGetSymbolAddress((void**)&gq,  g_q);
    cudaGetSymbolAddress((void**)&gk,  g_k);
    cudaGetSymbolAddress((void**)&gv,  g_v);
    cudaGetSymbolAddress((void**)&gao, g_ao);

    __nv_bfloat16 *xh, *xl, *dh, *dl, *aoh, *aol;
    __nv_bfloat16 *wqh, *wql, *wkh, *wkl, *wvh, *wvl, *woh, *wol;
    cudaGetSymbolAddress((void**)&xh,  g_xh);  cudaGetSymbolAddress((void**)&xl,  g_xl);
    cudaGetSymbolAddress((void**)&dh,  g_dh);  cudaGetSymbolAddress((void**)&dl,  g_dl);
    cudaGetSymbolAddress((void**)&aoh, g_aoh); cudaGetSymbolAddress((void**)&aol, g_aol);
    cudaGetSymbolAddress((void**)&wqh, g_wqh); cudaGetSymbolAddress((void**)&wql, g_wql);
    cudaGetSymbolAddress((void**)&wkh, g_wkh); cudaGetSymbolAddress((void**)&wkl, g_wkl);
    cudaGetSymbolAddress((void**)&wvh, g_wvh); cudaGetSymbolAddress((void**)&wvl, g_wvl);
    cudaGetSymbolAddress((void**)&woh, g_woh); cudaGetSymbolAddress((void**)&wol, g_wol);

    cudaFuncSetAttribute(attn_kernel, cudaFuncAttributeMaxDynamicSharedMemorySize, ATTN_SMEM);
    cudaFuncSetAttribute(gemm_mma_kernel, cudaFuncAttributeMaxDynamicSharedMemorySize, G_SMEM);

    const float qscale = 0.125f * 1.44269504088896341f;

    // conversions
    split_bf16_kernel<<<4096, 256>>>(x,  xh, xl, 4096 * 1024 / 4);
    split_bf16_kernel<<<2048, 256>>>(xd, dh, dl, 2048 * 1024 / 4);
    wsplit_transpose_kernel<<<dim3(32, 32), dim3(32, 8)>>>(Wq, wqh, wql);
    wsplit_transpose_kernel<<<dim3(32, 32), dim3(32, 8)>>>(Wk, wkh, wkl);
    wsplit_transpose_kernel<<<dim3(32, 32), dim3(32, 8)>>>(Wv, wvh, wvl);
    wsplit_transpose_kernel<<<dim3(32, 32), dim3(32, 8)>>>(Wo, woh, wol);

    // projections on tensor cores (mma.sync)
    gemm_mma_kernel<<<dim3(8, 32), 256, G_SMEM>>>(xh, xl, wqh, wql, nullptr, gq, qscale);
    gemm_mma_kernel<<<dim3(8, 16), 256, G_SMEM>>>(dh, dl, wkh, wkl, nullptr, gk, 1.0f);
    gemm_mma_kernel<<<dim3(8, 16), 256, G_SMEM>>>(dh, dl, wvh, wvl, nullptr, gv, 1.0f);

    attn_kernel<<<dim3(16, 16, 2), 256, ATTN_SMEM>>>(gq, gk, gv, gao);

    split_bf16_kernel<<<4096, 256>>>(gao, aoh, aol, 4096 * 1024 / 4);
    gemm_mma_kernel<<<dim3(8, 32), 256, G_SMEM>>>(aoh, aol, woh, wol, bo, out, 1.0f);
}

// round 4
// speedup vs baseline: 2.7661x; 1.6455x over previous
#include <cuda_runtime.h>
#include <cuda_bf16.h>
#include <cstdint>

// ============================ scratch (allocation-free) ============================
__device__ __nv_bfloat16 g_xh [4096 * 1024], g_xl [4096 * 1024];
__device__ __nv_bfloat16 g_dh [2048 * 1024], g_dl [2048 * 1024];
__device__ __nv_bfloat16 g_qph[4096 * 1024], g_qpl[4096 * 1024];
__device__ __nv_bfloat16 g_kph[2048 * 1024], g_kpl[2048 * 1024];
__device__ __nv_bfloat16 g_vph[2048 * 1024], g_vpl[2048 * 1024];
__device__ __nv_bfloat16 g_aoh[4096 * 1024], g_aol[4096 * 1024];
__device__ __nv_bfloat16 g_wqh[1024 * 1024], g_wql[1024 * 1024];
__device__ __nv_bfloat16 g_wkh[1024 * 1024], g_wkl[1024 * 1024];
__device__ __nv_bfloat16 g_wvh[1024 * 1024], g_wvl[1024 * 1024];
__device__ __nv_bfloat16 g_woh[1024 * 1024], g_wol[1024 * 1024];

// ============================ PTX helpers (arch-generic) ============================
__device__ __forceinline__ uint32_t smem_u32(const void* p) {
    uint32_t a;
    asm("{ .reg .u64 t; cvta.to.shared.u64 t, %1; cvt.u32.u64 %0, t; }" : "=r"(a) : "l"(p));
    return a;
}
__device__ __forceinline__ void ldsm_x4(uint32_t& r0, uint32_t& r1, uint32_t& r2, uint32_t& r3,
                                        uint32_t addr) {
    asm volatile("ldmatrix.sync.aligned.m8n8.x4.shared.b16 {%0,%1,%2,%3}, [%4];"
                 : "=r"(r0), "=r"(r1), "=r"(r2), "=r"(r3) : "r"(addr));
}
__device__ __forceinline__ void ldsm_x4_t(uint32_t& r0, uint32_t& r1, uint32_t& r2, uint32_t& r3,
                                          uint32_t addr) {
    asm volatile("ldmatrix.sync.aligned.m8n8.x4.trans.shared.b16 {%0,%1,%2,%3}, [%4];"
                 : "=r"(r0), "=r"(r1), "=r"(r2), "=r"(r3) : "r"(addr));
}
__device__ __forceinline__ void mma_bf16(float* d, const uint32_t* a, uint32_t b0, uint32_t b1) {
    asm volatile("mma.sync.aligned.m16n8k16.row.col.f32.bf16.bf16.f32 "
                 "{%0,%1,%2,%3}, {%4,%5,%6,%7}, {%8,%9}, {%0,%1,%2,%3};"
                 : "+f"(d[0]), "+f"(d[1]), "+f"(d[2]), "+f"(d[3])
                 : "r"(a[0]), "r"(a[1]), "r"(a[2]), "r"(a[3]), "r"(b0), "r"(b1));
}
__device__ __forceinline__ void cp_async16(uint32_t dst, const void* src) {
    asm volatile("cp.async.cg.shared.global [%0], [%1], 16;" :: "r"(dst), "l"(src) : "memory");
}
__device__ __forceinline__ void cp_commit() {
    asm volatile("cp.async.commit_group;" ::: "memory");
}

__device__ __forceinline__ float fexp2(float x) {
    x = fmaxf(x, -120.0f);
    float t = x + 12582912.0f;
    float f = x - (t - 12582912.0f);
    int   e = __float_as_int(t) << 23;
    float p = 1.33335581e-3f;
    p = fmaf(p, f, 9.61812911e-3f);
    p = fmaf(p, f, 5.55041087e-2f);
    p = fmaf(p, f, 2.40226507e-1f);
    p = fmaf(p, f, 6.93147181e-1f);
    p = fmaf(p, f, 1.0f);
    return __int_as_float(__float_as_int(p) + e);
}

// ============================ split / transpose conversions ============================
__global__ void split_bf16_kernel(const float* __restrict__ in,
                                  __nv_bfloat16* __restrict__ hi,
                                  __nv_bfloat16* __restrict__ lo, int n4) {
    int i = blockIdx.x * blockDim.x + threadIdx.x;
    if (i >= n4) return;
    float4 v = ((const float4*)in)[i];
    __nv_bfloat16 h0 = __float2bfloat16(v.x), h1 = __float2bfloat16(v.y);
    __nv_bfloat16 h2 = __float2bfloat16(v.z), h3 = __float2bfloat16(v.w);
    __nv_bfloat16 l0 = __float2bfloat16(v.x - __bfloat162float(h0));
    __nv_bfloat16 l1 = __float2bfloat16(v.y - __bfloat162float(h1));
    __nv_bfloat16 l2 = __float2bfloat16(v.z - __bfloat162float(h2));
    __nv_bfloat16 l3 = __float2bfloat16(v.w - __bfloat162float(h3));
    ((__nv_bfloat162*)hi)[2 * i + 0] = __halves2bfloat162(h0, h1);
    ((__nv_bfloat162*)hi)[2 * i + 1] = __halves2bfloat162(h2, h3);
    ((__nv_bfloat162*)lo)[2 * i + 0] = __halves2bfloat162(l0, l1);
    ((__nv_bfloat162*)lo)[2 * i + 1] = __halves2bfloat162(l2, l3);
}

__global__ void wsplit_transpose_kernel(const float* __restrict__ W,
                                        __nv_bfloat16* __restrict__ th,
                                        __nv_bfloat16* __restrict__ tl) {
    __shared__ float t[32][33];
    int x = blockIdx.x * 32 + threadIdx.x;
#pragma unroll
    for (int j = 0; j < 32; j += 8) {
        int kk = blockIdx.y * 32 + threadIdx.y + j;
        t[threadIdx.y + j][threadIdx.x] = W[kk * 1024 + x];
    }
    __syncthreads();
    int kx = blockIdx.y * 32 + threadIdx.x;
#pragma unroll
    for (int j = 0; j < 32; j += 8) {
        int n = blockIdx.x * 32 + threadIdx.y + j;
        float v = t[threadIdx.x][threadIdx.y + j];
        __nv_bfloat16 h = __float2bfloat16(v);
        __nv_bfloat16 l = __float2bfloat16(v - __bfloat162float(h));
        th[n * 1024 + kx] = h;
        tl[n * 1024 + kx] = l;
    }
}

// ============================ mma.sync compensated-bf16 GEMM ============================
#define GTS      72
#define GTILE_B  (128 * GTS * 2)
#define G_SMEM   (8 * GTILE_B)

__global__ __launch_bounds__(256, 1)
void gemm_mma_kernel(const __nv_bfloat16* __restrict__ Ah,
                     const __nv_bfloat16* __restrict__ Al,
                     const __nv_bfloat16* __restrict__ Bh,
                     const __nv_bfloat16* __restrict__ Bl,
                     float* __restrict__ Cf,
                     __nv_bfloat16* __restrict__ Ch,
                     __nv_bfloat16* __restrict__ Cl,
                     const float* __restrict__ bias, float alpha) {
    extern __shared__ char smem[];
    const uint32_t sbase = smem_u32(smem);
    const int tid  = threadIdx.x;
    const int lane = tid & 31;
    const int wid  = tid >> 5;
    const int wm   = wid & 3;
    const int wn   = wid >> 2;
    const int m0   = blockIdx.y * 128;
    const int n0   = blockIdx.x * 128;

    auto issue_loads = [&](int c, int s) {
#pragma unroll
        for (int it = 0; it < 16; it++) {
            const int part = it >> 2;
            const int w    = tid + (it & 3) * 256;
            const int row  = w >> 3;
            const int q    = w & 7;
            const __nv_bfloat16* base =
                (part == 0) ? Ah : (part == 1) ? Al : (part == 2) ? Bh : Bl;
            const int grow = (part < 2) ? (m0 + row) : (n0 + row);
            const void* src = base + ((size_t)grow << 10) + c * 64 + q * 8;
            uint32_t dst = sbase + (uint32_t)((s * 4 + part) * GTILE_B)
                         + (uint32_t)((row * GTS + q * 8) * 2);
            cp_async16(dst, src);
        }
        cp_commit();
    };

    float d[2][8][4];
#pragma unroll
    for (int mt = 0; mt < 2; mt++)
#pragma unroll
        for (int nt = 0; nt < 8; nt++)
#pragma unroll
            for (int e = 0; e < 4; e++) d[mt][nt][e] = 0.0f;

    issue_loads(0, 0);
    issue_loads(1, 1);

    for (int c = 0; c < 16; c++) {
        const int s = c & 1;
        asm volatile("cp.async.wait_group 1;" ::: "memory");
        __syncthreads();

        const uint32_t stage = sbase + (uint32_t)(s * 4 * GTILE_B);
#pragma unroll
        for (int pr = 0; pr < 3; pr++) {
            const int ap = (pr == 2) ? 1 : 0;
            const int bp = (pr == 1) ? 3 : 2;
            const uint32_t abase = stage + (uint32_t)(ap * GTILE_B);
            const uint32_t bbase = stage + (uint32_t)(bp * GTILE_B);
#pragma unroll
            for (int ks = 0; ks < 4; ks++) {
                const int k16 = ks * 16;
                uint32_t af[2][4];
#pragma unroll
                for (int mt = 0; mt < 2; mt++) {
                    uint32_t addr = abase +
                        (uint32_t)(((wm * 32 + mt * 16 + (lane & 15)) * GTS
                                    + k16 + ((lane >> 4) * 8)) * 2);
                    ldsm_x4(af[mt][0], af[mt][1], af[mt][2], af[mt][3], addr);
                }
                uint32_t bf[4][4];
#pragma unroll
                for (int g = 0; g < 4; g++) {
                    const int mrow = lane >> 3;
                    uint32_t addr = bbase +
                        (uint32_t)(((wn * 64 + g * 16 + (mrow & 2) * 4 + (lane & 7)) * GTS
                                    + k16 + ((mrow & 1) * 8)) * 2);
                    ldsm_x4(bf[g][0], bf[g][1], bf[g][2], bf[g][3], addr);
                }
#pragma unroll
                for (int mt = 0; mt < 2; mt++)
#pragma unroll
                    for (int nt = 0; nt < 8; nt++)
                        mma_bf16(d[mt][nt], af[mt],
                                 bf[nt >> 1][(nt & 1) * 2], bf[nt >> 1][(nt & 1) * 2 + 1]);
            }
        }
        __syncthreads();
        if (c + 2 < 16) issue_loads(c + 2, s);
        else            cp_commit();
    }

    // ---- epilogue: fp32 (+bias) or split bf16 hi/lo ----
#pragma unroll
    for (int mt = 0; mt < 2; mt++) {
        const int row0 = m0 + wm * 32 + mt * 16 + (lane >> 2);
#pragma unroll
        for (int nt = 0; nt < 8; nt++) {
            const int col = n0 + wn * 64 + nt * 8 + (lane & 3) * 2;
            float v0 = d[mt][nt][0] * alpha, v1 = d[mt][nt][1] * alpha;
            float v2 = d[mt][nt][2] * alpha, v3 = d[mt][nt][3] * alpha;
            if (Cf) {
                float bx = 0.0f, by = 0.0f;
                if (bias) { bx = bias[col]; by = bias[col + 1]; }
                *(float2*)(Cf + (size_t)row0 * 1024 + col)       = make_float2(v0 + bx, v1 + by);
                *(float2*)(Cf + (size_t)(row0 + 8) * 1024 + col) = make_float2(v2 + bx, v3 + by);
            } else {
                __nv_bfloat16 h0 = __float2bfloat16(v0), h1 = __float2bfloat16(v1);
                __nv_bfloat16 h2 = __float2bfloat16(v2), h3 = __float2bfloat16(v3);
                __nv_bfloat162 H0 = __halves2bfloat162(h0, h1);
                __nv_bfloat162 H1 = __halves2bfloat162(h2, h3);
                __nv_bfloat162 L0 = __halves2bfloat162(
                    __float2bfloat16(v0 - __bfloat162float(h0)),
                    __float2bfloat16(v1 - __bfloat162float(h1)));
                __nv_bfloat162 L1 = __halves2bfloat162(
                    __float2bfloat16(v2 - __bfloat162float(h2)),
                    __float2bfloat16(v3 - __bfloat162float(h3)));
                *(__nv_bfloat162*)(Ch + (size_t)row0 * 1024 + col)       = H0;
                *(__nv_bfloat162*)(Ch + (size_t)(row0 + 8) * 1024 + col) = H1;
                *(__nv_bfloat162*)(Cl + (size_t)row0 * 1024 + col)       = L0;
                *(__nv_bfloat162*)(Cl + (size_t)(row0 + 8) * 1024 + col) = L1;
            }
        }
    }
}

// ============================ tensor-core banded attention ============================
// grid (16 qtiles, 16 heads, 2 b), block 256 (8 warps x 16 rows).
// Q hi/lo persistent in smem; K/V hi/lo 64-key blocks double-buffered via cp.async.
// S = QhKh+QhKl+QlKh; online softmax in fragments; O += PhVh+PhVl+PlVh.
#define AQS     72                         // smem row stride (bf16)
#define A_QH    0
#define A_QL    9216
#define A_KV    18432                      // KV stages base (elems)
#define A_STAGE 18432                      // 4 tiles * 4608
#define A_TILE  4608                       // 64*72
#define ATTN_SMEM ((A_KV + 2 * A_STAGE) * 2)   // 110592 B

__global__ __launch_bounds__(256, 2)
void attn_mma_kernel(const __nv_bfloat16* __restrict__ qh, const __nv_bfloat16* __restrict__ ql,
                     const __nv_bfloat16* __restrict__ kh, const __nv_bfloat16* __restrict__ kl,
                     const __nv_bfloat16* __restrict__ vh, const __nv_bfloat16* __restrict__ vl,
                     __nv_bfloat16* __restrict__ oh, __nv_bfloat16* __restrict__ ol) {
    extern __shared__ char smem[];
    const uint32_t sbase = smem_u32(smem);
    const int tid = threadIdx.x, lane = tid & 31, w = tid >> 5;
    const int qt = blockIdx.x, h = blockIdx.y, b = blockIdx.z;
    const int qi0 = qt * 128;

    int u_start = 0;
    { int lim = qi0 - 1089; if (lim > 0) u_start = ((lim + 63) >> 6) << 6; }

    // Q load (cp.async group 0)
    {
        const __nv_bfloat16* qsrc0 = qh;
        const __nv_bfloat16* qsrc1 = ql;
#pragma unroll
        for (int it = 0; it < 8; it++) {
            int cid = tid + it * 256;
            int arr = cid >> 10, r = (cid >> 3) & 127, q = cid & 7;
            const __nv_bfloat16* bp = arr ? qsrc1 : qsrc0;
            const void* src = bp + ((size_t)(b * 2048 + qi0 + r) << 10) + h * 64 + q * 8;
            uint32_t dst = sbase + (uint32_t)(((arr ? A_QL : A_QH) + r * AQS + q * 8) * 2);
            cp_async16(dst, src);
        }
        cp_commit();
    }

    auto issue_kv = [&](int u0, int s) {
#pragma unroll
        for (int it = 0; it < 8; it++) {
            int cid = tid + it * 256;
            int t = cid >> 9, r = (cid >> 3) & 63, q = cid & 7;
            const __nv_bfloat16* bp = (t == 0) ? kh : (t == 1) ? kl : (t == 2) ? vh : vl;
            const void* src = bp + ((size_t)(b * 1024 + u0 + r) << 10) + h * 64 + q * 8;
            uint32_t dst = sbase + (uint32_t)((A_KV + s * A_STAGE + t * A_TILE + r * AQS + q * 8) * 2);
            cp_async16(dst, src);
        }
        cp_commit();
    };
    issue_kv(u_start, 0);

    float d[8][4];
#pragma unroll
    for (int nt = 0; nt < 8; nt++)
#pragma unroll
        for (int e = 0; e < 4; e++) d[nt][e] = 0.0f;
    float m0 = -1e30f, m1 = -1e30f, l0 = 0.0f, l1 = 0.0f;

    const int i0 = qi0 + w * 16 + (lane >> 2);
    const int i1 = i0 + 8;

    for (int u0 = u_start; u0 < 1024; u0 += 64) {
        const int st = ((u0 - u_start) >> 6) & 1;
        const bool more = (u0 + 64 < 1024);
        if (more) {
            issue_kv(u0 + 64, st ^ 1);
            asm volatile("cp.async.wait_group 1;" ::: "memory");
        } else {
            asm volatile("cp.async.wait_group 0;" ::: "memory");
        }
        __syncthreads();

        const uint32_t stg = sbase + (uint32_t)((A_KV + st * A_STAGE) * 2);

        // ---- S = Qh*Kh + Qh*Kl + Ql*Kh ----
        float s_[8][4];
#pragma unroll
        for (int nt = 0; nt < 8; nt++)
#pragma unroll
            for (int e = 0; e < 4; e++) s_[nt][e] = 0.0f;

#pragma unroll
        for (int pr = 0; pr < 3; pr++) {
            const uint32_t abase = sbase + (uint32_t)((pr == 2 ? A_QL : A_QH) * 2);
            const uint32_t bbase = stg + (uint32_t)((pr == 1 ? A_TILE : 0) * 2);
#pragma unroll
            for (int ks = 0; ks < 4; ks++) {
                uint32_t af[4];
                ldsm_x4(af[0], af[1], af[2], af[3],
                    abase + (uint32_t)(((w * 16 + (lane & 15)) * AQS + ks * 16 + (lane >> 4) * 8) * 2));
                uint32_t bf[4][4];
                const int mrow = lane >> 3;
#pragma unroll
                for (int g = 0; g < 4; g++)
                    ldsm_x4(bf[g][0], bf[g][1], bf[g][2], bf[g][3],
                        bbase + (uint32_t)(((g * 16 + (mrow & 2) * 4 + (lane & 7)) * AQS
                                            + ks * 16 + (mrow & 1) * 8) * 2));
#pragma unroll
                for (int nt = 0; nt < 8; nt++)
                    mma_bf16(s_[nt], af, bf[nt >> 1][(nt & 1) * 2], bf[nt >> 1][(nt & 1) * 2 + 1]);
            }
        }

        // ---- online softmax on fragments ----
        float rmax0 = -1e30f, rmax1 = -1e30f;
#pragma unroll
        for (int nt = 0; nt < 8; nt++) {
            const int uc = u0 + nt * 8 + (lane & 3) * 2;
#pragma unroll
            for (int e = 0; e < 4; e++) {
                const int u = uc + (e & 1);
                const int i = (e < 2) ? i0 : i1;
                const int mf = (u >= i - 2) + (u >= i - 1026);
                if (mf == 0) s_[nt][e] = -1e30f;
                if (e < 2) rmax0 = fmaxf(rmax0, s_[nt][e]);
                else       rmax1 = fmaxf(rmax1, s_[nt][e]);
            }
        }
        rmax0 = fmaxf(rmax0, __shfl_xor_sync(0xffffffffu, rmax0, 1));
        rmax0 = fmaxf(rmax0, __shfl_xor_sync(0xffffffffu, rmax0, 2));
        rmax1 = fmaxf(rmax1, __shfl_xor_sync(0xffffffffu, rmax1, 1));
        rmax1 = fmaxf(rmax1, __shfl_xor_sync(0xffffffffu, rmax1, 2));
        const float mn0 = fmaxf(m0, rmax0), mn1 = fmaxf(m1, rmax1);
        const float sc0 = fexp2(m0 - mn0),  sc1 = fexp2(m1 - mn1);
        m0 = mn0; m1 = mn1;
        l0 *= sc0; l1 *= sc1;
#pragma unroll
        for (int nt = 0; nt < 8; nt++) {
            d[nt][0] *= sc0; d[nt][1] *= sc0; d[nt][2] *= sc1; d[nt][3] *= sc1;
            const int uc = u0 + nt * 8 + (lane & 3) * 2;
#pragma unroll
            for (int e = 0; e < 4; e++) {
                const int u = uc + (e & 1);
                const int i = (e < 2) ? i0 : i1;
                const float mf = (float)((u >= i - 2) + (u >= i - 1026));
                const float p = mf * fexp2(s_[nt][e] - ((e < 2) ? mn0 : mn1));
                s_[nt][e] = p;
                if (e < 2) l0 += p; else l1 += p;
            }
        }

        // ---- O += Ph*Vh + Ph*Vl + Pl*Vh ----
#pragma unroll
        for (int ks = 0; ks < 4; ks++) {
            uint32_t ph[4], pl[4];
#pragma unroll
            for (int j = 0; j < 4; j++) {
                const int nt = 2 * ks + (j >> 1);
                const float p0 = s_[nt][(j & 1) * 2], p1 = s_[nt][(j & 1) * 2 + 1];
                const __nv_bfloat16 h0 = __float2bfloat16(p0), h1 = __float2bfloat16(p1);
                __nv_bfloat162 H = __halves2bfloat162(h0, h1);
                ph[j] = *reinterpret_cast<uint32_t*>(&H);
                __nv_bfloat162 L = __halves2bfloat162(
                    __float2bfloat16(p0 - __bfloat162float(h0)),
                    __float2bfloat16(p1 - __bfloat162float(h1)));
                pl[j] = *reinterpret_cast<uint32_t*>(&L);
            }
            const uint32_t voff = (uint32_t)(((ks * 16 + ((lane >> 3) & 1) * 8 + (lane & 7)) * AQS) * 2)
                                + (uint32_t)((lane >> 4) * 16);
#pragma unroll
            for (int t = 0; t < 4; t++) {
                uint32_t vhf[4], vlf[4];
                ldsm_x4_t(vhf[0], vhf[1], vhf[2], vhf[3],
                          stg + (uint32_t)(2 * A_TILE * 2) + voff + (uint32_t)(t * 32));
                ldsm_x4_t(vlf[0], vlf[1], vlf[2], vlf[3],
                          stg + (uint32_t)(3 * A_TILE * 2) + voff + (uint32_t)(t * 32));
#pragma unroll
                for (int sub = 0; sub < 2; sub++) {
                    const int nt = 2 * t + sub;
                    const int ix = sub * 2;
                    mma_bf16(d[nt], ph, vhf[ix], vhf[ix + 1]);
                    mma_bf16(d[nt], ph, vlf[ix], vlf[ix + 1]);
                    mma_bf16(d[nt], pl, vhf[ix], vhf[ix + 1]);
                }
            }
        }
        __syncthreads();
    }

    // ---- epilogue: normalize, split hi/lo, store ----
    l0 += __shfl_xor_sync(0xffffffffu, l0, 1);
    l0 += __shfl_xor_sync(0xffffffffu, l0, 2);
    l1 += __shfl_xor_sync(0xffffffffu, l1, 1);
    l1 += __shfl_xor_sync(0xffffffffu, l1, 2);
    const float inv0 = 1.0f / l0, inv1 = 1.0f / l1;
    const size_t row0 = (size_t)(b * 2048 + qi0 + w * 16 + (lane >> 2));
#pragma unroll
    for (int nt = 0; nt < 8; nt++) {
        const int col = h * 64 + nt * 8 + (lane & 3) * 2;
        float o0 = d[nt][0] * inv0, o1 = d[nt][1] * inv0;
        float o2 = d[nt][2] * inv1, o3 = d[nt][3] * inv1;
        __nv_bfloat16 h0 = __float2bfloat16(o0), h1 = __float2bfloat16(o1);
        __nv_bfloat16 h2 = __float2bfloat16(o2), h3 = __float2bfloat16(o3);
        __nv_bfloat162 H0 = __halves2bfloat162(h0, h1);
        __nv_bfloat162 H1 = __halves2bfloat162(h2, h3);
        __nv_bfloat162 L0 = __halves2bfloat162(__float2bfloat16(o0 - __bfloat162float(h0)),
                                               __float2bfloat16(o1 - __bfloat162float(h1)));
        __nv_bfloat162 L1 = __halves2bfloat162(__float2bfloat16(o2 - __bfloat162float(h2)),
                                               __float2bfloat16(o3 - __bfloat162float(h3)));
        *(__nv_bfloat162*)(oh + row0 * 1024 + col)       = H0;
        *(__nv_bfloat162*)(oh + (row0 + 8) * 1024 + col) = H1;
        *(__nv_bfloat162*)(ol + row0 * 1024 + col)       = L0;
        *(__nv_bfloat162*)(ol + (row0 + 8) * 1024 + col) = L1;
    }
}

// ============================ launch ============================
extern "C" void kernel_launch(void* const* d_in, const int* in_sizes, int n_in,
                              void* d_out, int out_size) {
    const float* x  = (const float*)d_in[0];
    const float* xd = (const float*)d_in[1];
    const float* Wq = (const float*)d_in[2];
    const float* Wk = (const float*)d_in[3];
    const float* Wv = (const float*)d_in[4];
    const float* Wo = (const float*)d_in[5];
    const float* bo = (const float*)d_in[6];
    float* out = (float*)d_out;

    __nv_bfloat16 *xh, *xl, *dh, *dl;
    __nv_bfloat16 *qph, *qpl, *kph, *kpl, *vph, *vpl, *aoh, *aol;
    __nv_bfloat16 *wqh, *wql, *wkh, *wkl, *wvh, *wvl, *woh, *wol;
    cudaGetSymbolAddress((void**)&xh,  g_xh);  cudaGetSymbolAddress((void**)&xl,  g_xl);
    cudaGetSymbolAddress((void**)&dh,  g_dh);  cudaGetSymbolAddress((void**)&dl,  g_dl);
    cudaGetSymbolAddress((void**)&qph, g_qph); cudaGetSymbolAddress((void**)&qpl, g_qpl);
    cudaGetSymbolAddress((void**)&kph, g_kph); cudaGetSymbolAddress((void**)&kpl, g_kpl);
    cudaGetSymbolAddress((void**)&vph, g_vph); cudaGetSymbolAddress((void**)&vpl, g_vpl);
    cudaGetSymbolAddress((void**)&aoh, g_aoh); cudaGetSymbolAddress((void**)&aol, g_aol);
    cudaGetSymbolAddress((void**)&wqh, g_wqh); cudaGetSymbolAddress((void**)&wql, g_wql);
    cudaGetSymbolAddress((void**)&wkh, g_wkh); cudaGetSymbolAddress((void**)&wkl, g_wkl);
    cudaGetSymbolAddress((void**)&wvh, g_wvh); cudaGetSymbolAddress((void**)&wvl, g_wvl);
    cudaGetSymbolAddress((void**)&woh, g_woh); cudaGetSymbolAddress((void**)&wol, g_wol);

    cudaFuncSetAttribute(gemm_mma_kernel, cudaFuncAttributeMaxDynamicSharedMemorySize, G_SMEM);
    cudaFuncSetAttribute(attn_mma_kernel, cudaFuncAttributeMaxDynamicSharedMemorySize, ATTN_SMEM);

    const float qscale = 0.125f * 1.44269504088896341f;

    split_bf16_kernel<<<4096, 256>>>(x,  xh, xl, 4096 * 1024 / 4);
    split_bf16_kernel<<<2048, 256>>>(xd, dh, dl, 2048 * 1024 / 4);
    wsplit_transpose_kernel<<<dim3(32, 32), dim3(32, 8)>>>(Wq, wqh, wql);
    wsplit_transpose_kernel<<<dim3(32, 32), dim3(32, 8)>>>(Wk, wkh, wkl);
    wsplit_transpose_kernel<<<dim3(32, 32), dim3(32, 8)>>>(Wv, wvh, wvl);
    wsplit_transpose_kernel<<<dim3(32, 32), dim3(32, 8)>>>(Wo, woh, wol);

    // projections -> bf16 hi/lo directly (q pre-scaled by softmax scale * log2e)
    gemm_mma_kernel<<<dim3(8, 32), 256, G_SMEM>>>(xh, xl, wqh, wql, nullptr, qph, qpl, nullptr, qscale);
    gemm_mma_kernel<<<dim3(8, 16), 256, G_SMEM>>>(dh, dl, wkh, wkl, nullptr, kph, kpl, nullptr, 1.0f);
    gemm_mma_kernel<<<dim3(8, 16), 256, G_SMEM>>>(dh, dl, wvh, wvl, nullptr, vph, vpl, nullptr, 1.0f);

    attn_mma_kernel<<<dim3(16, 16, 2), 256, ATTN_SMEM>>>(qph, qpl, kph, kpl, vph, vpl, aoh, aol);

    gemm_mma_kernel<<<dim3(8, 32), 256, G_SMEM>>>(aoh, aol, woh, wol, out, nullptr, nullptr, bo, 1.0f);
}

// round 5
// speedup vs baseline: 3.7065x; 1.3400x over previous
#include <cuda_runtime.h>
#include <cuda_fp16.h>
#include <cstdint>

// ============================ scratch (allocation-free) ============================
__device__ __half g_x16[4096 * 1024];                     // x fp16
__device__ __half g_d16[2048 * 1024];                     // xd fp16
__device__ __half g_q16[4096 * 1024];                     // scaled q fp16
__device__ __half g_kh [2048 * 1024], g_kl [2048 * 1024];
__device__ __half g_vh [2048 * 1024], g_vl [2048 * 1024];
__device__ __half g_ao [4096 * 1024];                     // attn out fp16
__device__ __half g_wqh[1024 * 1024], g_wql[1024 * 1024];
__device__ __half g_wkh[1024 * 1024], g_wkl[1024 * 1024];
__device__ __half g_wvh[1024 * 1024], g_wvl[1024 * 1024];
__device__ __half g_woh[1024 * 1024], g_wol[1024 * 1024];

// ============================ PTX helpers (arch-generic) ============================
__device__ __forceinline__ uint32_t smem_u32(const void* p) {
    uint32_t a;
    asm("{ .reg .u64 t; cvta.to.shared.u64 t, %1; cvt.u32.u64 %0, t; }" : "=r"(a) : "l"(p));
    return a;
}
__device__ __forceinline__ void ldsm_x4(uint32_t& r0, uint32_t& r1, uint32_t& r2, uint32_t& r3,
                                        uint32_t addr) {
    asm volatile("ldmatrix.sync.aligned.m8n8.x4.shared.b16 {%0,%1,%2,%3}, [%4];"
                 : "=r"(r0), "=r"(r1), "=r"(r2), "=r"(r3) : "r"(addr));
}
__device__ __forceinline__ void ldsm_x4_t(uint32_t& r0, uint32_t& r1, uint32_t& r2, uint32_t& r3,
                                          uint32_t addr) {
    asm volatile("ldmatrix.sync.aligned.m8n8.x4.trans.shared.b16 {%0,%1,%2,%3}, [%4];"
                 : "=r"(r0), "=r"(r1), "=r"(r2), "=r"(r3) : "r"(addr));
}
__device__ __forceinline__ void mma_f16(float* d, const uint32_t* a, uint32_t b0, uint32_t b1) {
    asm volatile("mma.sync.aligned.m16n8k16.row.col.f32.f16.f16.f32 "
                 "{%0,%1,%2,%3}, {%4,%5,%6,%7}, {%8,%9}, {%0,%1,%2,%3};"
                 : "+f"(d[0]), "+f"(d[1]), "+f"(d[2]), "+f"(d[3])
                 : "r"(a[0]), "r"(a[1]), "r"(a[2]), "r"(a[3]), "r"(b0), "r"(b1));
}
__device__ __forceinline__ void cp_async16(uint32_t dst, const void* src) {
    asm volatile("cp.async.cg.shared.global [%0], [%1], 16;" :: "r"(dst), "l"(src) : "memory");
}
__device__ __forceinline__ void cp_commit() {
    asm volatile("cp.async.commit_group;" ::: "memory");
}

__device__ __forceinline__ float fexp2(float x) {
    x = fmaxf(x, -120.0f);
    float t = x + 12582912.0f;
    float f = x - (t - 12582912.0f);
    int   e = __float_as_int(t) << 23;
    float p = 1.33335581e-3f;
    p = fmaf(p, f, 9.61812911e-3f);
    p = fmaf(p, f, 5.55041087e-2f);
    p = fmaf(p, f, 2.40226507e-1f);
    p = fmaf(p, f, 6.93147181e-1f);
    p = fmaf(p, f, 1.0f);
    return __int_as_float(__float_as_int(p) + e);
}

// ============================ conversions ============================
__global__ void cast_f16_kernel(const float* __restrict__ in, __half* __restrict__ out, int n4) {
    int i = blockIdx.x * blockDim.x + threadIdx.x;
    if (i >= n4) return;
    float4 v = ((const float4*)in)[i];
    ((__half2*)out)[2 * i + 0] = __floats2half2_rn(v.x, v.y);
    ((__half2*)out)[2 * i + 1] = __floats2half2_rn(v.z, v.w);
}

// W [1024 k][1024 n] row-major -> Wt hi/lo [n][k] fp16
__global__ void wsplit_transpose_kernel(const float* __restrict__ W,
                                        __half* __restrict__ th,
                                        __half* __restrict__ tl) {
    __shared__ float t[32][33];
    int x = blockIdx.x * 32 + threadIdx.x;
#pragma unroll
    for (int j = 0; j < 32; j += 8) {
        int kk = blockIdx.y * 32 + threadIdx.y + j;
        t[threadIdx.y + j][threadIdx.x] = W[kk * 1024 + x];
    }
    __syncthreads();
    int kx = blockIdx.y * 32 + threadIdx.x;
#pragma unroll
    for (int j = 0; j < 32; j += 8) {
        int n = blockIdx.x * 32 + threadIdx.y + j;
        float v = t[threadIdx.x][threadIdx.y + j];
        __half h = __float2half_rn(v);
        __half l = __float2half_rn(v - __half2float(h));
        th[n * 1024 + kx] = h;
        tl[n * 1024 + kx] = l;
    }
}

// ============================ fp16 2-term GEMM (A single, B hi/lo) ============================
// C = alpha * A @ (Bh + Bl)  [+bias]; outputs fp32, fp16-single, or fp16 hi/lo
#define GTS      72
#define GTILE_B  (128 * GTS * 2)        // 18432
#define G_SMEM   (6 * GTILE_B)          // 110592 -> 2 CTAs/SM

__global__ __launch_bounds__(256, 2)
void gemm_mma_kernel(const __half* __restrict__ A,
                     const __half* __restrict__ Bh,
                     const __half* __restrict__ Bl,
                     float* __restrict__ Cf,
                     __half* __restrict__ Ch,
                     __half* __restrict__ Cl,
                     const float* __restrict__ bias, float alpha) {
    extern __shared__ char smem[];
    const uint32_t sbase = smem_u32(smem);
    const int tid  = threadIdx.x;
    const int lane = tid & 31;
    const int wid  = tid >> 5;
    const int wm   = wid & 3;
    const int wn   = wid >> 2;
    const int m0   = blockIdx.y * 128;
    const int n0   = blockIdx.x * 128;

    auto issue_loads = [&](int c, int s) {
#pragma unroll
        for (int it = 0; it < 12; it++) {
            const int part = it >> 2;                    // 0=A 1=Bh 2=Bl
            const int w    = tid + (it & 3) * 256;       // 0..1023
            const int row  = w >> 3;
            const int q    = w & 7;
            const __half* base = (part == 0) ? A : (part == 1) ? Bh : Bl;
            const int grow = (part == 0) ? (m0 + row) : (n0 + row);
            const void* src = base + ((size_t)grow << 10) + c * 64 + q * 8;
            uint32_t dst = sbase + (uint32_t)((s * 3 + part) * GTILE_B)
                         + (uint32_t)((row * GTS + q * 8) * 2);
            cp_async16(dst, src);
        }
        cp_commit();
    };

    float d[2][8][4];
#pragma unroll
    for (int mt = 0; mt < 2; mt++)
#pragma unroll
        for (int nt = 0; nt < 8; nt++)
#pragma unroll
            for (int e = 0; e < 4; e++) d[mt][nt][e] = 0.0f;

    issue_loads(0, 0);
    issue_loads(1, 1);

    for (int c = 0; c < 16; c++) {
        const int s = c & 1;
        asm volatile("cp.async.wait_group 1;" ::: "memory");
        __syncthreads();

        const uint32_t stage = sbase + (uint32_t)(s * 3 * GTILE_B);
#pragma unroll
        for (int ks = 0; ks < 4; ks++) {
            const int k16 = ks * 16;
            uint32_t af[2][4];
#pragma unroll
            for (int mt = 0; mt < 2; mt++) {
                uint32_t addr = stage +
                    (uint32_t)(((wm * 32 + mt * 16 + (lane & 15)) * GTS
                                + k16 + ((lane >> 4) * 8)) * 2);
                ldsm_x4(af[mt][0], af[mt][1], af[mt][2], af[mt][3], addr);
            }
            const int mrow = lane >> 3;
#pragma unroll
            for (int bp = 1; bp <= 2; bp++) {
                const uint32_t bbase = stage + (uint32_t)(bp * GTILE_B);
                uint32_t bf[4][4];
#pragma unroll
                for (int g = 0; g < 4; g++) {
                    uint32_t addr = bbase +
                        (uint32_t)(((wn * 64 + g * 16 + (mrow & 2) * 4 + (lane & 7)) * GTS
                                    + k16 + ((mrow & 1) * 8)) * 2);
                    ldsm_x4(bf[g][0], bf[g][1], bf[g][2], bf[g][3], addr);
                }
#pragma unroll
                for (int mt = 0; mt < 2; mt++)
#pragma unroll
                    for (int nt = 0; nt < 8; nt++)
                        mma_f16(d[mt][nt], af[mt],
                                bf[nt >> 1][(nt & 1) * 2], bf[nt >> 1][(nt & 1) * 2 + 1]);
            }
        }
        __syncthreads();
        if (c + 2 < 16) issue_loads(c + 2, s);
        else            cp_commit();
    }

    // ---- epilogue ----
#pragma unroll
    for (int mt = 0; mt < 2; mt++) {
        const int row0 = m0 + wm * 32 + mt * 16 + (lane >> 2);
#pragma unroll
        for (int nt = 0; nt < 8; nt++) {
            const int col = n0 + wn * 64 + nt * 8 + (lane & 3) * 2;
            float v0 = d[mt][nt][0] * alpha, v1 = d[mt][nt][1] * alpha;
            float v2 = d[mt][nt][2] * alpha, v3 = d[mt][nt][3] * alpha;
            if (Cf) {
                float bx = 0.0f, by = 0.0f;
                if (bias) { bx = bias[col]; by = bias[col + 1]; }
                *(float2*)(Cf + (size_t)row0 * 1024 + col)       = make_float2(v0 + bx, v1 + by);
                *(float2*)(Cf + (size_t)(row0 + 8) * 1024 + col) = make_float2(v2 + bx, v3 + by);
            } else if (!Cl) {
                *(__half2*)(Ch + (size_t)row0 * 1024 + col)       = __floats2half2_rn(v0, v1);
                *(__half2*)(Ch + (size_t)(row0 + 8) * 1024 + col) = __floats2half2_rn(v2, v3);
            } else {
                __half h0 = __float2half_rn(v0), h1 = __float2half_rn(v1);
                __half h2 = __float2half_rn(v2), h3 = __float2half_rn(v3);
                *(__half2*)(Ch + (size_t)row0 * 1024 + col)       = __halves2half2(h0, h1);
                *(__half2*)(Ch + (size_t)(row0 + 8) * 1024 + col) = __halves2half2(h2, h3);
                *(__half2*)(Cl + (size_t)row0 * 1024 + col)       = __halves2half2(
                    __float2half_rn(v0 - __half2float(h0)), __float2half_rn(v1 - __half2float(h1)));
                *(__half2*)(Cl + (size_t)(row0 + 8) * 1024 + col) = __halves2half2(
                    __float2half_rn(v2 - __half2float(h2)), __float2half_rn(v3 - __half2float(h3)));
            }
        }
    }
}

// ============================ tensor-core banded attention ============================
// Q single fp16 persistent; K hi/lo + V hi/lo double-buffered.
// S = Q*Kh + Q*Kl (2 MMAs); O += Ph*Vh + Ph*Vl + Pl*Vh (3 MMAs).
#define AQS     72
#define A_Q     0                       // 128*72 = 9216 elems
#define A_KV    9216
#define A_STAGE 18432                   // 4 tiles * 4608
#define A_TILE  4608
#define ATTN_SMEM ((A_KV + 2 * A_STAGE) * 2)   // 92160 B

__global__ __launch_bounds__(256, 2)
void attn_mma_kernel(const __half* __restrict__ q,
                     const __half* __restrict__ kh, const __half* __restrict__ kl,
                     const __half* __restrict__ vh, const __half* __restrict__ vl,
                     __half* __restrict__ o) {
    extern __shared__ char smem[];
    const uint32_t sbase = smem_u32(smem);
    const int tid = threadIdx.x, lane = tid & 31, w = tid >> 5;
    const int qt = blockIdx.x, h = blockIdx.y, b = blockIdx.z;
    const int qi0 = qt * 128;

    int u_start = 0;
    { int lim = qi0 - 1089; if (lim > 0) u_start = ((lim + 63) >> 6) << 6; }

    // Q load (group 0): 128 rows x 8 chunks = 1024
    {
#pragma unroll
        for (int it = 0; it < 4; it++) {
            int cid = tid + it * 256;
            int r = cid >> 3, qq = cid & 7;
            const void* src = q + ((size_t)(b * 2048 + qi0 + r) << 10) + h * 64 + qq * 8;
            uint32_t dst = sbase + (uint32_t)((A_Q + r * AQS + qq * 8) * 2);
            cp_async16(dst, src);
        }
        cp_commit();
    }

    auto issue_kv = [&](int u0, int s) {
#pragma unroll
        for (int it = 0; it < 8; it++) {
            int cid = tid + it * 256;
            int t = cid >> 9, r = (cid >> 3) & 63, qq = cid & 7;
            const __half* bp = (t == 0) ? kh : (t == 1) ? kl : (t == 2) ? vh : vl;
            const void* src = bp + ((size_t)(b * 1024 + u0 + r) << 10) + h * 64 + qq * 8;
            uint32_t dst = sbase + (uint32_t)((A_KV + s * A_STAGE + t * A_TILE + r * AQS + qq * 8) * 2);
            cp_async16(dst, src);
        }
        cp_commit();
    };
    issue_kv(u_start, 0);

    float d[8][4];
#pragma unroll
    for (int nt = 0; nt < 8; nt++)
#pragma unroll
        for (int e = 0; e < 4; e++) d[nt][e] = 0.0f;
    float m0 = -1e30f, m1 = -1e30f, l0 = 0.0f, l1 = 0.0f;

    const int i0 = qi0 + w * 16 + (lane >> 2);
    const int i1 = i0 + 8;

    for (int u0 = u_start; u0 < 1024; u0 += 64) {
        const int st = ((u0 - u_start) >> 6) & 1;
        const bool more = (u0 + 64 < 1024);
        if (more) {
            issue_kv(u0 + 64, st ^ 1);
            asm volatile("cp.async.wait_group 1;" ::: "memory");
        } else {
            asm volatile("cp.async.wait_group 0;" ::: "memory");
        }
        __syncthreads();

        const uint32_t stg = sbase + (uint32_t)((A_KV + st * A_STAGE) * 2);

        // ---- S = Q*Kh + Q*Kl ----
        float s_[8][4];
#pragma unroll
        for (int nt = 0; nt < 8; nt++)
#pragma unroll
            for (int e = 0; e < 4; e++) s_[nt][e] = 0.0f;

#pragma unroll
        for (int ks = 0; ks < 4; ks++) {
            uint32_t af[4];
            ldsm_x4(af[0], af[1], af[2], af[3],
                sbase + (uint32_t)(((w * 16 + (lane & 15)) * AQS + ks * 16 + (lane >> 4) * 8) * 2));
            const int mrow = lane >> 3;
#pragma unroll
            for (int pr = 0; pr < 2; pr++) {
                const uint32_t bbase = stg + (uint32_t)(pr * A_TILE * 2);
                uint32_t bf[4][4];
#pragma unroll
                for (int g = 0; g < 4; g++)
                    ldsm_x4(bf[g][0], bf[g][1], bf[g][2], bf[g][3],
                        bbase + (uint32_t)(((g * 16 + (mrow & 2) * 4 + (lane & 7)) * AQS
                                            + ks * 16 + (mrow & 1) * 8) * 2));
#pragma unroll
                for (int nt = 0; nt < 8; nt++)
                    mma_f16(s_[nt], af, bf[nt >> 1][(nt & 1) * 2], bf[nt >> 1][(nt & 1) * 2 + 1]);
            }
        }

        // ---- online softmax ----
        float rmax0 = -1e30f, rmax1 = -1e30f;
#pragma unroll
        for (int nt = 0; nt < 8; nt++) {
            const int uc = u0 + nt * 8 + (lane & 3) * 2;
#pragma unroll
            for (int e = 0; e < 4; e++) {
                const int u = uc + (e & 1);
                const int i = (e < 2) ? i0 : i1;
                const int mf = (u >= i - 2) + (u >= i - 1026);
                if (mf == 0) s_[nt][e] = -1e30f;
                if (e < 2) rmax0 = fmaxf(rmax0, s_[nt][e]);
                else       rmax1 = fmaxf(rmax1, s_[nt][e]);
            }
        }
        rmax0 = fmaxf(rmax0, __shfl_xor_sync(0xffffffffu, rmax0, 1));
        rmax0 = fmaxf(rmax0, __shfl_xor_sync(0xffffffffu, rmax0, 2));
        rmax1 = fmaxf(rmax1, __shfl_xor_sync(0xffffffffu, rmax1, 1));
        rmax1 = fmaxf(rmax1, __shfl_xor_sync(0xffffffffu, rmax1, 2));
        const float mn0 = fmaxf(m0, rmax0), mn1 = fmaxf(m1, rmax1);
        const float sc0 = fexp2(m0 - mn0),  sc1 = fexp2(m1 - mn1);
        m0 = mn0; m1 = mn1;
        l0 *= sc0; l1 *= sc1;
#pragma unroll
        for (int nt = 0; nt < 8; nt++) {
            d[nt][0] *= sc0; d[nt][1] *= sc0; d[nt][2] *= sc1; d[nt][3] *= sc1;
            const int uc = u0 + nt * 8 + (lane & 3) * 2;
#pragma unroll
            for (int e = 0; e < 4; e++) {
                const int u = uc + (e & 1);
                const int i = (e < 2) ? i0 : i1;
                const float mf = (float)((u >= i - 2) + (u >= i - 1026));
                const float p = mf * fexp2(s_[nt][e] - ((e < 2) ? mn0 : mn1));
                s_[nt][e] = p;
                if (e < 2) l0 += p; else l1 += p;
            }
        }

        // ---- O += Ph*Vh + Ph*Vl + Pl*Vh ----
#pragma unroll
        for (int ks = 0; ks < 4; ks++) {
            uint32_t ph[4], pl[4];
#pragma unroll
            for (int j = 0; j < 4; j++) {
                const int nt = 2 * ks + (j >> 1);
                const float p0 = s_[nt][(j & 1) * 2], p1 = s_[nt][(j & 1) * 2 + 1];
                const __half h0 = __float2half_rn(p0), h1 = __float2half_rn(p1);
                __half2 H = __halves2half2(h0, h1);
                ph[j] = *reinterpret_cast<uint32_t*>(&H);
                __half2 L = __halves2half2(__float2half_rn(p0 - __half2float(h0)),
                                           __float2half_rn(p1 - __half2float(h1)));
                pl[j] = *reinterpret_cast<uint32_t*>(&L);
            }
            const uint32_t voff = (uint32_t)(((ks * 16 + ((lane >> 3) & 1) * 8 + (lane & 7)) * AQS) * 2)
                                + (uint32_t)((lane >> 4) * 16);
#pragma unroll
            for (int t = 0; t < 4; t++) {
                uint32_t vhf[4], vlf[4];
                ldsm_x4_t(vhf[0], vhf[1], vhf[2], vhf[3],
                          stg + (uint32_t)(2 * A_TILE * 2) + voff + (uint32_t)(t * 32));
                ldsm_x4_t(vlf[0], vlf[1], vlf[2], vlf[3],
                          stg + (uint32_t)(3 * A_TILE * 2) + voff + (uint32_t)(t * 32));
#pragma unroll
                for (int sub = 0; sub < 2; sub++) {
                    const int nt = 2 * t + sub;
                    const int ix = sub * 2;
                    mma_f16(d[nt], ph, vhf[ix], vhf[ix + 1]);
                    mma_f16(d[nt], ph, vlf[ix], vlf[ix + 1]);
                    mma_f16(d[nt], pl, vhf[ix], vhf[ix + 1]);
                }
            }
        }
        __syncthreads();
    }

    // ---- epilogue: normalize, single fp16 store ----
    l0 += __shfl_xor_sync(0xffffffffu, l0, 1);
    l0 += __shfl_xor_sync(0xffffffffu, l0, 2);
    l1 += __shfl_xor_sync(0xffffffffu, l1, 1);
    l1 += __shfl_xor_sync(0xffffffffu, l1, 2);
    const float inv0 = 1.0f / l0, inv1 = 1.0f / l1;
    const size_t row0 = (size_t)(b * 2048 + qi0 + w * 16 + (lane >> 2));
#pragma unroll
    for (int nt = 0; nt < 8; nt++) {
        const int col = h * 64 + nt * 8 + (lane & 3) * 2;
        *(__half2*)(o + row0 * 1024 + col)       = __floats2half2_rn(d[nt][0] * inv0, d[nt][1] * inv0);
        *(__half2*)(o + (row0 + 8) * 1024 + col) = __floats2half2_rn(d[nt][2] * inv1, d[nt][3] * inv1);
    }
}

// ============================ launch ============================
extern "C" void kernel_launch(void* const* d_in, const int* in_sizes, int n_in,
                              void* d_out, int out_size) {
    const float* x  = (const float*)d_in[0];
    const float* xd = (const float*)d_in[1];
    const float* Wq = (const float*)d_in[2];
    const float* Wk = (const float*)d_in[3];
    const float* Wv = (const float*)d_in[4];
    const float* Wo = (const float*)d_in[5];
    const float* bo = (const float*)d_in[6];
    float* out = (float*)d_out;

    __half *x16, *d16, *q16, *kh, *kl, *vh, *vl, *ao;
    __half *wqh, *wql, *wkh, *wkl, *wvh, *wvl, *woh, *wol;
    cudaGetSymbolAddress((void**)&x16, g_x16);  cudaGetSymbolAddress((void**)&d16, g_d16);
    cudaGetSymbolAddress((void**)&q16, g_q16);
    cudaGetSymbolAddress((void**)&kh,  g_kh);   cudaGetSymbolAddress((void**)&kl,  g_kl);
    cudaGetSymbolAddress((void**)&vh,  g_vh);   cudaGetSymbolAddress((void**)&vl,  g_vl);
    cudaGetSymbolAddress((void**)&ao,  g_ao);
    cudaGetSymbolAddress((void**)&wqh, g_wqh);  cudaGetSymbolAddress((void**)&wql, g_wql);
    cudaGetSymbolAddress((void**)&wkh, g_wkh);  cudaGetSymbolAddress((void**)&wkl, g_wkl);
    cudaGetSymbolAddress((void**)&wvh, g_wvh);  cudaGetSymbolAddress((void**)&wvl, g_wvl);
    cudaGetSymbolAddress((void**)&woh, g_woh);  cudaGetSymbolAddress((void**)&wol, g_wol);

    cudaFuncSetAttribute(gemm_mma_kernel, cudaFuncAttributeMaxDynamicSharedMemorySize, G_SMEM);
    cudaFuncSetAttribute(attn_mma_kernel, cudaFuncAttributeMaxDynamicSharedMemorySize, ATTN_SMEM);

    const float qscale = 0.125f * 1.44269504088896341f;

    cast_f16_kernel<<<4096, 256>>>(x,  x16, 4096 * 1024 / 4);
    cast_f16_kernel<<<2048, 256>>>(xd, d16, 2048 * 1024 / 4);
    wsplit_transpose_kernel<<<dim3(32, 32), dim3(32, 8)>>>(Wq, wqh, wql);
    wsplit_transpose_kernel<<<dim3(32, 32), dim3(32, 8)>>>(Wk, wkh, wkl);
    wsplit_transpose_kernel<<<dim3(32, 32), dim3(32, 8)>>>(Wv, wvh, wvl);
    wsplit_transpose_kernel<<<dim3(32, 32), dim3(32, 8)>>>(Wo, woh, wol);

    // projections: q single fp16 (pre-scaled); k, v fp16 hi/lo
    gemm_mma_kernel<<<dim3(8, 32), 256, G_SMEM>>>(x16, wqh, wql, nullptr, q16, nullptr, nullptr, qscale);
    gemm_mma_kernel<<<dim3(8, 16), 256, G_SMEM>>>(d16, wkh, wkl, nullptr, kh, kl, nullptr, 1.0f);
    gemm_mma_kernel<<<dim3(8, 16), 256, G_SMEM>>>(d16, wvh, wvl, nullptr, vh, vl, nullptr, 1.0f);

    attn_mma_kernel<<<dim3(16, 16, 2), 256, ATTN_SMEM>>>(q16, kh, kl, vh, vl, ao);

    gemm_mma_kernel<<<dim3(8, 32), 256, G_SMEM>>>(ao, woh, wol, out, nullptr, nullptr, bo, 1.0f);
}

// round 6
// speedup vs baseline: 4.7523x; 1.2821x over previous
#include <cuda_runtime.h>
#include <cuda_fp16.h>
#include <cstdint>

// ============================ scratch (allocation-free) ============================
__device__ __half g_x16[4096 * 1024];
__device__ __half g_d16[2048 * 1024];
__device__ __half g_q16[4096 * 1024];
__device__ __half g_k16[2048 * 1024];
__device__ __half g_vh [2048 * 1024], g_vl [2048 * 1024];
__device__ __half g_ao [4096 * 1024];
__device__ __half g_wqh[1024 * 1024];
__device__ __half g_wkh[1024 * 1024];
__device__ __half g_wvh[1024 * 1024], g_wvl[1024 * 1024];
__device__ __half g_woh[1024 * 1024], g_wol[1024 * 1024];

// ============================ PTX helpers (arch-generic) ============================
__device__ __forceinline__ uint32_t smem_u32(const void* p) {
    uint32_t a;
    asm("{ .reg .u64 t; cvta.to.shared.u64 t, %1; cvt.u32.u64 %0, t; }" : "=r"(a) : "l"(p));
    return a;
}
__device__ __forceinline__ void ldsm_x4(uint32_t& r0, uint32_t& r1, uint32_t& r2, uint32_t& r3,
                                        uint32_t addr) {
    asm volatile("ldmatrix.sync.aligned.m8n8.x4.shared.b16 {%0,%1,%2,%3}, [%4];"
                 : "=r"(r0), "=r"(r1), "=r"(r2), "=r"(r3) : "r"(addr));
}
__device__ __forceinline__ void ldsm_x4_t(uint32_t& r0, uint32_t& r1, uint32_t& r2, uint32_t& r3,
                                          uint32_t addr) {
    asm volatile("ldmatrix.sync.aligned.m8n8.x4.trans.shared.b16 {%0,%1,%2,%3}, [%4];"
                 : "=r"(r0), "=r"(r1), "=r"(r2), "=r"(r3) : "r"(addr));
}
__device__ __forceinline__ void mma_f16(float* d, const uint32_t* a, uint32_t b0, uint32_t b1) {
    asm volatile("mma.sync.aligned.m16n8k16.row.col.f32.f16.f16.f32 "
                 "{%0,%1,%2,%3}, {%4,%5,%6,%7}, {%8,%9}, {%0,%1,%2,%3};"
                 : "+f"(d[0]), "+f"(d[1]), "+f"(d[2]), "+f"(d[3])
                 : "r"(a[0]), "r"(a[1]), "r"(a[2]), "r"(a[3]), "r"(b0), "r"(b1));
}
__device__ __forceinline__ void cp_async16(uint32_t dst, const void* src) {
    asm volatile("cp.async.cg.shared.global [%0], [%1], 16;" :: "r"(dst), "l"(src) : "memory");
}
__device__ __forceinline__ void cp_commit() {
    asm volatile("cp.async.commit_group;" ::: "memory");
}

__device__ __forceinline__ float fexp2(float x) {
    x = fmaxf(x, -120.0f);
    float t = x + 12582912.0f;
    float f = x - (t - 12582912.0f);
    int   e = __float_as_int(t) << 23;
    float p = 1.33335581e-3f;
    p = fmaf(p, f, 9.61812911e-3f);
    p = fmaf(p, f, 5.55041087e-2f);
    p = fmaf(p, f, 2.40226507e-1f);
    p = fmaf(p, f, 6.93147181e-1f);
    p = fmaf(p, f, 1.0f);
    return __int_as_float(__float_as_int(p) + e);
}

// ============================ conversions ============================
__global__ void cast_f16_kernel(const float* __restrict__ in, __half* __restrict__ out, int n4) {
    int i = blockIdx.x * blockDim.x + threadIdx.x;
    if (i >= n4) return;
    float4 v = ((const float4*)in)[i];
    ((__half2*)out)[2 * i + 0] = __floats2half2_rn(v.x, v.y);
    ((__half2*)out)[2 * i + 1] = __floats2half2_rn(v.z, v.w);
}

// W [1024 k][1024 n] row-major -> Wt [n][k] fp16 (hi only, or hi+lo)
__global__ void wsplit_transpose_kernel(const float* __restrict__ W,
                                        __half* __restrict__ th,
                                        __half* __restrict__ tl) {
    __shared__ float t[32][33];
    int x = blockIdx.x * 32 + threadIdx.x;
#pragma unroll
    for (int j = 0; j < 32; j += 8) {
        int kk = blockIdx.y * 32 + threadIdx.y + j;
        t[threadIdx.y + j][threadIdx.x] = W[kk * 1024 + x];
    }
    __syncthreads();
    int kx = blockIdx.y * 32 + threadIdx.x;
#pragma unroll
    for (int j = 0; j < 32; j += 8) {
        int n = blockIdx.x * 32 + threadIdx.y + j;
        float v = t[threadIdx.x][threadIdx.y + j];
        __half h = __float2half_rn(v);
        th[n * 1024 + kx] = h;
        if (tl) tl[n * 1024 + kx] = __float2half_rn(v - __half2float(h));
    }
}

// ============================ fp16 GEMM (A single, B with BT terms) ============================
#define GTS      72
#define GTILE_B  (128 * GTS * 2)        // 18432

template<int BT>                         // tiles/stage = 1+BT
__global__ __launch_bounds__(256, 2)
void gemm_mma_kernel(const __half* __restrict__ A,
                     const __half* __restrict__ Bh,
                     const __half* __restrict__ Bl,
                     float* __restrict__ Cf,
                     __half* __restrict__ Ch,
                     __half* __restrict__ Cl,
                     const float* __restrict__ bias, float alpha) {
    extern __shared__ char smem[];
    const uint32_t sbase = smem_u32(smem);
    const int tid  = threadIdx.x;
    const int lane = tid & 31;
    const int wid  = tid >> 5;
    const int wm   = wid & 3;
    const int wn   = wid >> 2;
    const int m0   = blockIdx.y * 128;
    const int n0   = blockIdx.x * 128;
    constexpr int TPS = 1 + BT;          // tiles per stage

    auto issue_loads = [&](int c, int s) {
#pragma unroll
        for (int it = 0; it < 4 * TPS; it++) {
            const int part = it >> 2;                    // 0=A, 1=Bh, 2=Bl
            const int w    = tid + (it & 3) * 256;
            const int row  = w >> 3;
            const int q    = w & 7;
            const __half* base = (part == 0) ? A : (part == 1) ? Bh : Bl;
            const int grow = (part == 0) ? (m0 + row) : (n0 + row);
            const void* src = base + ((size_t)grow << 10) + c * 64 + q * 8;
            uint32_t dst = sbase + (uint32_t)((s * TPS + part) * GTILE_B)
                         + (uint32_t)((row * GTS + q * 8) * 2);
            cp_async16(dst, src);
        }
        cp_commit();
    };

    float d[2][8][4];
#pragma unroll
    for (int mt = 0; mt < 2; mt++)
#pragma unroll
        for (int nt = 0; nt < 8; nt++)
#pragma unroll
            for (int e = 0; e < 4; e++) d[mt][nt][e] = 0.0f;

    issue_loads(0, 0);
    issue_loads(1, 1);

    for (int c = 0; c < 16; c++) {
        const int s = c & 1;
        asm volatile("cp.async.wait_group 1;" ::: "memory");
        __syncthreads();

        const uint32_t stage = sbase + (uint32_t)(s * TPS * GTILE_B);
#pragma unroll
        for (int ks = 0; ks < 4; ks++) {
            const int k16 = ks * 16;
            uint32_t af[2][4];
#pragma unroll
            for (int mt = 0; mt < 2; mt++) {
                uint32_t addr = stage +
                    (uint32_t)(((wm * 32 + mt * 16 + (lane & 15)) * GTS
                                + k16 + ((lane >> 4) * 8)) * 2);
                ldsm_x4(af[mt][0], af[mt][1], af[mt][2], af[mt][3], addr);
            }
            const int mrow = lane >> 3;
#pragma unroll
            for (int bp = 1; bp <= BT; bp++) {
                const uint32_t bbase = stage + (uint32_t)(bp * GTILE_B);
                uint32_t bf[4][4];
#pragma unroll
                for (int g = 0; g < 4; g++) {
                    uint32_t addr = bbase +
                        (uint32_t)(((wn * 64 + g * 16 + (mrow & 2) * 4 + (lane & 7)) * GTS
                                    + k16 + ((mrow & 1) * 8)) * 2);
                    ldsm_x4(bf[g][0], bf[g][1], bf[g][2], bf[g][3], addr);
                }
#pragma unroll
                for (int mt = 0; mt < 2; mt++)
#pragma unroll
                    for (int nt = 0; nt < 8; nt++)
                        mma_f16(d[mt][nt], af[mt],
                                bf[nt >> 1][(nt & 1) * 2], bf[nt >> 1][(nt & 1) * 2 + 1]);
            }
        }
        __syncthreads();
        if (c + 2 < 16) issue_loads(c + 2, s);
        else            cp_commit();
    }

    // ---- epilogue ----
#pragma unroll
    for (int mt = 0; mt < 2; mt++) {
        const int row0 = m0 + wm * 32 + mt * 16 + (lane >> 2);
#pragma unroll
        for (int nt = 0; nt < 8; nt++) {
            const int col = n0 + wn * 64 + nt * 8 + (lane & 3) * 2;
            float v0 = d[mt][nt][0] * alpha, v1 = d[mt][nt][1] * alpha;
            float v2 = d[mt][nt][2] * alpha, v3 = d[mt][nt][3] * alpha;
            if (Cf) {
                float bx = 0.0f, by = 0.0f;
                if (bias) { bx = bias[col]; by = bias[col + 1]; }
                *(float2*)(Cf + (size_t)row0 * 1024 + col)       = make_float2(v0 + bx, v1 + by);
                *(float2*)(Cf + (size_t)(row0 + 8) * 1024 + col) = make_float2(v2 + bx, v3 + by);
            } else if (!Cl) {
                *(__half2*)(Ch + (size_t)row0 * 1024 + col)       = __floats2half2_rn(v0, v1);
                *(__half2*)(Ch + (size_t)(row0 + 8) * 1024 + col) = __floats2half2_rn(v2, v3);
            } else {
                __half h0 = __float2half_rn(v0), h1 = __float2half_rn(v1);
                __half h2 = __float2half_rn(v2), h3 = __float2half_rn(v3);
                *(__half2*)(Ch + (size_t)row0 * 1024 + col)       = __halves2half2(h0, h1);
                *(__half2*)(Ch + (size_t)(row0 + 8) * 1024 + col) = __halves2half2(h2, h3);
                *(__half2*)(Cl + (size_t)row0 * 1024 + col)       = __halves2half2(
                    __float2half_rn(v0 - __half2float(h0)), __float2half_rn(v1 - __half2float(h1)));
                *(__half2*)(Cl + (size_t)(row0 + 8) * 1024 + col) = __halves2half2(
                    __float2half_rn(v2 - __half2float(h2)), __float2half_rn(v3 - __half2float(h3)));
            }
        }
    }
}

#define G_SMEM1 (4 * GTILE_B)            // 1-term: 73728
#define G_SMEM2 (6 * GTILE_B)            // 2-term: 110592

// ============================ tensor-core banded attention ============================
// Q single fp16 persistent; K single + V hi/lo double-buffered.
// S = Q*K (1 set); O += Ph*Vh + Ph*Vl (2 sets).
#define AQS     72
#define A_Q     0                        // 128*72 = 9216 elems
#define A_KV    9216
#define A_TILE  4608                     // 64*72
#define A_STAGE (3 * A_TILE)             // K, Vh, Vl
#define ATTN_SMEM ((A_KV + 2 * A_STAGE) * 2)   // 73728 B

__global__ __launch_bounds__(256, 2)
void attn_mma_kernel(const __half* __restrict__ q,
                     const __half* __restrict__ k16,
                     const __half* __restrict__ vh, const __half* __restrict__ vl,
                     __half* __restrict__ o) {
    extern __shared__ char smem[];
    const uint32_t sbase = smem_u32(smem);
    const int tid = threadIdx.x, lane = tid & 31, w = tid >> 5;
    const int qt = blockIdx.x, h = blockIdx.y, b = blockIdx.z;
    const int qi0 = qt * 128;

    int u_start = 0;
    { int lim = qi0 - 1089; if (lim > 0) u_start = ((lim + 63) >> 6) << 6; }

    // Q load (group 0)
    {
#pragma unroll
        for (int it = 0; it < 4; it++) {
            int cid = tid + it * 256;
            int r = cid >> 3, qq = cid & 7;
            const void* src = q + ((size_t)(b * 2048 + qi0 + r) << 10) + h * 64 + qq * 8;
            uint32_t dst = sbase + (uint32_t)((A_Q + r * AQS + qq * 8) * 2);
            cp_async16(dst, src);
        }
        cp_commit();
    }

    auto issue_kv = [&](int u0, int s) {
#pragma unroll
        for (int it = 0; it < 6; it++) {
            int cid = tid + it * 256;
            int t = cid >> 9, r = (cid >> 3) & 63, qq = cid & 7;
            const __half* bp = (t == 0) ? k16 : (t == 1) ? vh : vl;
            const void* src = bp + ((size_t)(b * 1024 + u0 + r) << 10) + h * 64 + qq * 8;
            uint32_t dst = sbase + (uint32_t)((A_KV + s * A_STAGE + t * A_TILE + r * AQS + qq * 8) * 2);
            cp_async16(dst, src);
        }
        cp_commit();
    };
    issue_kv(u_start, 0);

    float d[8][4];
#pragma unroll
    for (int nt = 0; nt < 8; nt++)
#pragma unroll
        for (int e = 0; e < 4; e++) d[nt][e] = 0.0f;
    float m0 = -1e30f, m1 = -1e30f, l0 = 0.0f, l1 = 0.0f;

    const int i0 = qi0 + w * 16 + (lane >> 2);
    const int i1 = i0 + 8;

    for (int u0 = u_start; u0 < 1024; u0 += 64) {
        const int st = ((u0 - u_start) >> 6) & 1;
        const bool more = (u0 + 64 < 1024);
        if (more) {
            issue_kv(u0 + 64, st ^ 1);
            asm volatile("cp.async.wait_group 1;" ::: "memory");
        } else {
            asm volatile("cp.async.wait_group 0;" ::: "memory");
        }
        __syncthreads();

        const uint32_t stg = sbase + (uint32_t)((A_KV + st * A_STAGE) * 2);

        // ---- S = Q * K ----
        float s_[8][4];
#pragma unroll
        for (int nt = 0; nt < 8; nt++)
#pragma unroll
            for (int e = 0; e < 4; e++) s_[nt][e] = 0.0f;

#pragma unroll
        for (int ks = 0; ks < 4; ks++) {
            uint32_t af[4];
            ldsm_x4(af[0], af[1], af[2], af[3],
                sbase + (uint32_t)(((w * 16 + (lane & 15)) * AQS + ks * 16 + (lane >> 4) * 8) * 2));
            const int mrow = lane >> 3;
            uint32_t bf[4][4];
#pragma unroll
            for (int g = 0; g < 4; g++)
                ldsm_x4(bf[g][0], bf[g][1], bf[g][2], bf[g][3],
                    stg + (uint32_t)(((g * 16 + (mrow & 2) * 4 + (lane & 7)) * AQS
                                      + ks * 16 + (mrow & 1) * 8) * 2));
#pragma unroll
            for (int nt = 0; nt < 8; nt++)
                mma_f16(s_[nt], af, bf[nt >> 1][(nt & 1) * 2], bf[nt >> 1][(nt & 1) * 2 + 1]);
        }

        // ---- online softmax ----
        float rmax0 = -1e30f, rmax1 = -1e30f;
#pragma unroll
        for (int nt = 0; nt < 8; nt++) {
            const int uc = u0 + nt * 8 + (lane & 3) * 2;
#pragma unroll
            for (int e = 0; e < 4; e++) {
                const int u = uc + (e & 1);
                const int i = (e < 2) ? i0 : i1;
                const int mf = (u >= i - 2) + (u >= i - 1026);
                if (mf == 0) s_[nt][e] = -1e30f;
                if (e < 2) rmax0 = fmaxf(rmax0, s_[nt][e]);
                else       rmax1 = fmaxf(rmax1, s_[nt][e]);
            }
        }
        rmax0 = fmaxf(rmax0, __shfl_xor_sync(0xffffffffu, rmax0, 1));
        rmax0 = fmaxf(rmax0, __shfl_xor_sync(0xffffffffu, rmax0, 2));
        rmax1 = fmaxf(rmax1, __shfl_xor_sync(0xffffffffu, rmax1, 1));
        rmax1 = fmaxf(rmax1, __shfl_xor_sync(0xffffffffu, rmax1, 2));
        const float mn0 = fmaxf(m0, rmax0), mn1 = fmaxf(m1, rmax1);
        const float sc0 = fexp2(m0 - mn0),  sc1 = fexp2(m1 - mn1);
        m0 = mn0; m1 = mn1;
        l0 *= sc0; l1 *= sc1;
#pragma unroll
        for (int nt = 0; nt < 8; nt++) {
            d[nt][0] *= sc0; d[nt][1] *= sc0; d[nt][2] *= sc1; d[nt][3] *= sc1;
            const int uc = u0 + nt * 8 + (lane & 3) * 2;
#pragma unroll
            for (int e = 0; e < 4; e++) {
                const int u = uc + (e & 1);
                const int i = (e < 2) ? i0 : i1;
                const float mf = (float)((u >= i - 2) + (u >= i - 1026));
                const float p = mf * fexp2(s_[nt][e] - ((e < 2) ? mn0 : mn1));
                s_[nt][e] = p;
                if (e < 2) l0 += p; else l1 += p;
            }
        }

        // ---- O += Ph*Vh + Ph*Vl ----
#pragma unroll
        for (int ks = 0; ks < 4; ks++) {
            uint32_t ph[4];
#pragma unroll
            for (int j = 0; j < 4; j++) {
                const int nt = 2 * ks + (j >> 1);
                __half2 H = __floats2half2_rn(s_[nt][(j & 1) * 2], s_[nt][(j & 1) * 2 + 1]);
                ph[j] = *reinterpret_cast<uint32_t*>(&H);
            }
            const uint32_t voff = (uint32_t)(((ks * 16 + ((lane >> 3) & 1) * 8 + (lane & 7)) * AQS) * 2)
                                + (uint32_t)((lane >> 4) * 16);
#pragma unroll
            for (int t = 0; t < 4; t++) {
                uint32_t vhf[4], vlf[4];
                ldsm_x4_t(vhf[0], vhf[1], vhf[2], vhf[3],
                          stg + (uint32_t)(1 * A_TILE * 2) + voff + (uint32_t)(t * 32));
                ldsm_x4_t(vlf[0], vlf[1], vlf[2], vlf[3],
                          stg + (uint32_t)(2 * A_TILE * 2) + voff + (uint32_t)(t * 32));
#pragma unroll
                for (int sub = 0; sub < 2; sub++) {
                    const int nt = 2 * t + sub;
                    const int ix = sub * 2;
                    mma_f16(d[nt], ph, vhf[ix], vhf[ix + 1]);
                    mma_f16(d[nt], ph, vlf[ix], vlf[ix + 1]);
                }
            }
        }
        __syncthreads();
    }

    // ---- epilogue ----
    l0 += __shfl_xor_sync(0xffffffffu, l0, 1);
    l0 += __shfl_xor_sync(0xffffffffu, l0, 2);
    l1 += __shfl_xor_sync(0xffffffffu, l1, 1);
    l1 += __shfl_xor_sync(0xffffffffu, l1, 2);
    const float inv0 = 1.0f / l0, inv1 = 1.0f / l1;
    const size_t row0 = (size_t)(b * 2048 + qi0 + w * 16 + (lane >> 2));
#pragma unroll
    for (int nt = 0; nt < 8; nt++) {
        const int col = h * 64 + nt * 8 + (lane & 3) * 2;
        *(__half2*)(o + row0 * 1024 + col)       = __floats2half2_rn(d[nt][0] * inv0, d[nt][1] * inv0);
        *(__half2*)(o + (row0 + 8) * 1024 + col) = __floats2half2_rn(d[nt][2] * inv1, d[nt][3] * inv1);
    }
}

// ============================ launch ============================
extern "C" void kernel_launch(void* const* d_in, const int* in_sizes, int n_in,
                              void* d_out, int out_size) {
    const float* x  = (const float*)d_in[0];
    const float* xd = (const float*)d_in[1];
    const float* Wq = (const float*)d_in[2];
    const float* Wk = (const float*)d_in[3];
    const float* Wv = (const float*)d_in[4];
    const float* Wo = (const float*)d_in[5];
    const float* bo = (const float*)d_in[6];
    float* out = (float*)d_out;

    __half *x16, *d16, *q16, *k16, *vh, *vl, *ao;
    __half *wqh, *wkh, *wvh, *wvl, *woh, *wol;
    cudaGetSymbolAddress((void**)&x16, g_x16);  cudaGetSymbolAddress((void**)&d16, g_d16);
    cudaGetSymbolAddress((void**)&q16, g_q16);  cudaGetSymbolAddress((void**)&k16, g_k16);
    cudaGetSymbolAddress((void**)&vh,  g_vh);   cudaGetSymbolAddress((void**)&vl,  g_vl);
    cudaGetSymbolAddress((void**)&ao,  g_ao);
    cudaGetSymbolAddress((void**)&wqh, g_wqh);  cudaGetSymbolAddress((void**)&wkh, g_wkh);
    cudaGetSymbolAddress((void**)&wvh, g_wvh);  cudaGetSymbolAddress((void**)&wvl, g_wvl);
    cudaGetSymbolAddress((void**)&woh, g_woh);  cudaGetSymbolAddress((void**)&wol, g_wol);

    cudaFuncSetAttribute(gemm_mma_kernel<1>, cudaFuncAttributeMaxDynamicSharedMemorySize, G_SMEM1);
    cudaFuncSetAttribute(gemm_mma_kernel<2>, cudaFuncAttributeMaxDynamicSharedMemorySize, G_SMEM2);
    cudaFuncSetAttribute(attn_mma_kernel, cudaFuncAttributeMaxDynamicSharedMemorySize, ATTN_SMEM);

    const float qscale = 0.125f * 1.44269504088896341f;

    cast_f16_kernel<<<4096, 256>>>(x,  x16, 4096 * 1024 / 4);
    cast_f16_kernel<<<2048, 256>>>(xd, d16, 2048 * 1024 / 4);
    wsplit_transpose_kernel<<<dim3(32, 32), dim3(32, 8)>>>(Wq, wqh, nullptr);
    wsplit_transpose_kernel<<<dim3(32, 32), dim3(32, 8)>>>(Wk, wkh, nullptr);
    wsplit_transpose_kernel<<<dim3(32, 32), dim3(32, 8)>>>(Wv, wvh, wvl);
    wsplit_transpose_kernel<<<dim3(32, 32), dim3(32, 8)>>>(Wo, woh, wol);

    // projections: q,k single-term fp16; v 2-term -> hi/lo
    gemm_mma_kernel<1><<<dim3(8, 32), 256, G_SMEM1>>>(x16, wqh, nullptr, nullptr, q16, nullptr, nullptr, qscale);
    gemm_mma_kernel<1><<<dim3(8, 16), 256, G_SMEM1>>>(d16, wkh, nullptr, nullptr, k16, nullptr, nullptr, 1.0f);
    gemm_mma_kernel<2><<<dim3(8, 16), 256, G_SMEM2>>>(d16, wvh, wvl, nullptr, vh, vl, nullptr, 1.0f);

    attn_mma_kernel<<<dim3(16, 16, 2), 256, ATTN_SMEM>>>(q16, k16, vh, vl, ao);

    gemm_mma_kernel<2><<<dim3(8, 32), 256, G_SMEM2>>>(ao, woh, wol, out, nullptr, nullptr, bo, 1.0f);
}

// round 7
// speedup vs baseline: 6.2774x; 1.3209x over previous
#include <cuda_runtime.h>
#include <cuda_fp16.h>
#include <cstdint>

// ============================ scratch (allocation-free) ============================
__device__ __half g_x16[4096 * 1024];
__device__ __half g_d16[2048 * 1024];
__device__ __half g_q16[4096 * 1024];
__device__ __half g_k16[2048 * 1024];
__device__ __half g_v16[2048 * 1024];
__device__ __half g_ao [4096 * 1024];
__device__ __half g_wq [1024 * 1024];
__device__ __half g_wk [1024 * 1024];
__device__ __half g_wv [1024 * 1024];
__device__ __half g_wo [1024 * 1024];

// ============================ PTX helpers (arch-generic) ============================
__device__ __forceinline__ uint32_t smem_u32(const void* p) {
    uint32_t a;
    asm("{ .reg .u64 t; cvta.to.shared.u64 t, %1; cvt.u32.u64 %0, t; }" : "=r"(a) : "l"(p));
    return a;
}
__device__ __forceinline__ void ldsm_x4(uint32_t& r0, uint32_t& r1, uint32_t& r2, uint32_t& r3,
                                        uint32_t addr) {
    asm volatile("ldmatrix.sync.aligned.m8n8.x4.shared.b16 {%0,%1,%2,%3}, [%4];"
                 : "=r"(r0), "=r"(r1), "=r"(r2), "=r"(r3) : "r"(addr));
}
__device__ __forceinline__ void ldsm_x4_t(uint32_t& r0, uint32_t& r1, uint32_t& r2, uint32_t& r3,
                                          uint32_t addr) {
    asm volatile("ldmatrix.sync.aligned.m8n8.x4.trans.shared.b16 {%0,%1,%2,%3}, [%4];"
                 : "=r"(r0), "=r"(r1), "=r"(r2), "=r"(r3) : "r"(addr));
}
__device__ __forceinline__ void mma_f16(float* d, const uint32_t* a, uint32_t b0, uint32_t b1) {
    asm volatile("mma.sync.aligned.m16n8k16.row.col.f32.f16.f16.f32 "
                 "{%0,%1,%2,%3}, {%4,%5,%6,%7}, {%8,%9}, {%0,%1,%2,%3};"
                 : "+f"(d[0]), "+f"(d[1]), "+f"(d[2]), "+f"(d[3])
                 : "r"(a[0]), "r"(a[1]), "r"(a[2]), "r"(a[3]), "r"(b0), "r"(b1));
}
__device__ __forceinline__ void cp_async16(uint32_t dst, const void* src) {
    asm volatile("cp.async.cg.shared.global [%0], [%1], 16;" :: "r"(dst), "l"(src) : "memory");
}
__device__ __forceinline__ void cp_commit() {
    asm volatile("cp.async.commit_group;" ::: "memory");
}

__device__ __forceinline__ float fexp2(float x) {
    x = fmaxf(x, -120.0f);
    float t = x + 12582912.0f;
    float f = x - (t - 12582912.0f);
    int   e = __float_as_int(t) << 23;
    float p = 1.33335581e-3f;
    p = fmaf(p, f, 9.61812911e-3f);
    p = fmaf(p, f, 5.55041087e-2f);
    p = fmaf(p, f, 2.40226507e-1f);
    p = fmaf(p, f, 6.93147181e-1f);
    p = fmaf(p, f, 1.0f);
    return __int_as_float(__float_as_int(p) + e);
}

// ============================ conversions ============================
__global__ void cast_f16_kernel(const float* __restrict__ in, __half* __restrict__ out, int n4) {
    int i = blockIdx.x * blockDim.x + threadIdx.x;
    if (i >= n4) return;
    float4 v = ((const float4*)in)[i];
    ((__half2*)out)[2 * i + 0] = __floats2half2_rn(v.x, v.y);
    ((__half2*)out)[2 * i + 1] = __floats2half2_rn(v.z, v.w);
}

// all 4 weights: [1024 k][1024 n] row-major -> [n][k] fp16, one launch (z selects)
__global__ void wsplit_all_kernel(const float* __restrict__ W0, const float* __restrict__ W1,
                                  const float* __restrict__ W2, const float* __restrict__ W3,
                                  __half* __restrict__ T0, __half* __restrict__ T1,
                                  __half* __restrict__ T2, __half* __restrict__ T3) {
    const int z = blockIdx.z;
    const float* W = (z == 0) ? W0 : (z == 1) ? W1 : (z == 2) ? W2 : W3;
    __half* T = (z == 0) ? T0 : (z == 1) ? T1 : (z == 2) ? T2 : T3;
    __shared__ float t[32][33];
    int x = blockIdx.x * 32 + threadIdx.x;
#pragma unroll
    for (int j = 0; j < 32; j += 8) {
        int kk = blockIdx.y * 32 + threadIdx.y + j;
        t[threadIdx.y + j][threadIdx.x] = W[kk * 1024 + x];
    }
    __syncthreads();
    int kx = blockIdx.y * 32 + threadIdx.x;
#pragma unroll
    for (int j = 0; j < 32; j += 8) {
        int n = blockIdx.x * 32 + threadIdx.y + j;
        T[n * 1024 + kx] = __float2half_rn(t[threadIdx.x][threadIdx.y + j]);
    }
}

// ============================ fp16 1-term GEMM core ============================
#define GTS      72
#define GTILE_B  (128 * GTS * 2)        // 18432
#define G_SMEM   (4 * GTILE_B)          // A,B x 2 stages = 73728

struct GemmCore {
    // runs the full mainloop; leaves accumulators in d
    __device__ static void run(float d[2][8][4], const __half* A, const __half* B,
                               uint32_t sbase, int m0, int n0, int tid) {
        const int lane = tid & 31;
        const int wid  = tid >> 5;
        const int wm   = wid & 3;
        const int wn   = wid >> 2;

        auto issue_loads = [&](int c, int s) {
#pragma unroll
            for (int it = 0; it < 8; it++) {
                const int part = it >> 2;               // 0=A, 1=B
                const int w    = tid + (it & 3) * 256;
                const int row  = w >> 3;
                const int q    = w & 7;
                const __half* base = part ? B : A;
                const int grow = part ? (n0 + row) : (m0 + row);
                const void* src = base + ((size_t)grow << 10) + c * 64 + q * 8;
                uint32_t dst = sbase + (uint32_t)((s * 2 + part) * GTILE_B)
                             + (uint32_t)((row * GTS + q * 8) * 2);
                cp_async16(dst, src);
            }
            cp_commit();
        };

#pragma unroll
        for (int mt = 0; mt < 2; mt++)
#pragma unroll
            for (int nt = 0; nt < 8; nt++)
#pragma unroll
                for (int e = 0; e < 4; e++) d[mt][nt][e] = 0.0f;

        issue_loads(0, 0);
        issue_loads(1, 1);

        for (int c = 0; c < 16; c++) {
            const int s = c & 1;
            asm volatile("cp.async.wait_group 1;" ::: "memory");
            __syncthreads();

            const uint32_t stage = sbase + (uint32_t)(s * 2 * GTILE_B);
            const uint32_t bbase = stage + (uint32_t)GTILE_B;
#pragma unroll
            for (int ks = 0; ks < 4; ks++) {
                const int k16 = ks * 16;
                uint32_t af[2][4];
#pragma unroll
                for (int mt = 0; mt < 2; mt++) {
                    uint32_t addr = stage +
                        (uint32_t)(((wm * 32 + mt * 16 + (lane & 15)) * GTS
                                    + k16 + ((lane >> 4) * 8)) * 2);
                    ldsm_x4(af[mt][0], af[mt][1], af[mt][2], af[mt][3], addr);
                }
                const int mrow = lane >> 3;
                uint32_t bf[4][4];
#pragma unroll
                for (int g = 0; g < 4; g++) {
                    uint32_t addr = bbase +
                        (uint32_t)(((wn * 64 + g * 16 + (mrow & 2) * 4 + (lane & 7)) * GTS
                                    + k16 + ((mrow & 1) * 8)) * 2);
                    ldsm_x4(bf[g][0], bf[g][1], bf[g][2], bf[g][3], addr);
                }
#pragma unroll
                for (int mt = 0; mt < 2; mt++)
#pragma unroll
                    for (int nt = 0; nt < 8; nt++)
                        mma_f16(d[mt][nt], af[mt],
                                bf[nt >> 1][(nt & 1) * 2], bf[nt >> 1][(nt & 1) * 2 + 1]);
            }
            __syncthreads();
            if (c + 2 < 16) issue_loads(c + 2, s);
            else            cp_commit();
        }
    }
};

// merged q/k/v projection: grid (8, 64); by<32: q, by<48: k, else v. fp16 out.
__global__ __launch_bounds__(256, 2)
void gemm_qkv_kernel(const __half* __restrict__ x16, const __half* __restrict__ d16,
                     const __half* __restrict__ wq, const __half* __restrict__ wk,
                     const __half* __restrict__ wv,
                     __half* __restrict__ q16, __half* __restrict__ k16,
                     __half* __restrict__ v16, float qscale) {
    extern __shared__ char smem[];
    const uint32_t sbase = smem_u32(smem);
    const int tid = threadIdx.x;
    const int by  = blockIdx.y;

    const __half* A; const __half* B; __half* C; float alpha; int m0;
    if (by < 32)      { A = x16; B = wq; C = q16; alpha = qscale; m0 = by * 128; }
    else if (by < 48) { A = d16; B = wk; C = k16; alpha = 1.0f;   m0 = (by - 32) * 128; }
    else              { A = d16; B = wv; C = v16; alpha = 1.0f;   m0 = (by - 48) * 128; }
    const int n0 = blockIdx.x * 128;

    float d[2][8][4];
    GemmCore::run(d, A, B, sbase, m0, n0, tid);

    const int lane = tid & 31, wid = tid >> 5, wm = wid & 3, wn = wid >> 2;
#pragma unroll
    for (int mt = 0; mt < 2; mt++) {
        const int row0 = m0 + wm * 32 + mt * 16 + (lane >> 2);
#pragma unroll
        for (int nt = 0; nt < 8; nt++) {
            const int col = n0 + wn * 64 + nt * 8 + (lane & 3) * 2;
            *(__half2*)(C + (size_t)row0 * 1024 + col) =
                __floats2half2_rn(d[mt][nt][0] * alpha, d[mt][nt][1] * alpha);
            *(__half2*)(C + (size_t)(row0 + 8) * 1024 + col) =
                __floats2half2_rn(d[mt][nt][2] * alpha, d[mt][nt][3] * alpha);
        }
    }
}

// output projection: fp32 + bias
__global__ __launch_bounds__(256, 2)
void gemm_o_kernel(const __half* __restrict__ A, const __half* __restrict__ B,
                   float* __restrict__ Cf, const float* __restrict__ bias) {
    extern __shared__ char smem[];
    const uint32_t sbase = smem_u32(smem);
    const int tid = threadIdx.x;
    const int m0 = blockIdx.y * 128;
    const int n0 = blockIdx.x * 128;

    float d[2][8][4];
    GemmCore::run(d, A, B, sbase, m0, n0, tid);

    const int lane = tid & 31, wid = tid >> 5, wm = wid & 3, wn = wid >> 2;
#pragma unroll
    for (int mt = 0; mt < 2; mt++) {
        const int row0 = m0 + wm * 32 + mt * 16 + (lane >> 2);
#pragma unroll
        for (int nt = 0; nt < 8; nt++) {
            const int col = n0 + wn * 64 + nt * 8 + (lane & 3) * 2;
            const float bx = bias[col], by = bias[col + 1];
            *(float2*)(Cf + (size_t)row0 * 1024 + col) =
                make_float2(d[mt][nt][0] + bx, d[mt][nt][1] + by);
            *(float2*)(Cf + (size_t)(row0 + 8) * 1024 + col) =
                make_float2(d[mt][nt][2] + bx, d[mt][nt][3] + by);
        }
    }
}

// ============================ tensor-core banded attention ============================
// Q persistent; K + V (single fp16 each) double-buffered.
// S = Q*K (1 set); O += P*V (1 set).
#define AQS     72
#define A_Q     0                        // 128*72 = 9216 elems
#define A_KV    9216
#define A_TILE  4608                     // 64*72
#define A_STAGE (2 * A_TILE)             // K, V
#define ATTN_SMEM ((A_KV + 2 * A_STAGE) * 2)   // 55296 B

__global__ __launch_bounds__(256, 2)
void attn_mma_kernel(const __half* __restrict__ q,
                     const __half* __restrict__ k16,
                     const __half* __restrict__ v16,
                     __half* __restrict__ o) {
    extern __shared__ char smem[];
    const uint32_t sbase = smem_u32(smem);
    const int tid = threadIdx.x, lane = tid & 31, w = tid >> 5;
    const int qt = blockIdx.x, h = blockIdx.y, b = blockIdx.z;
    const int qi0 = qt * 128;

    int u_start = 0;
    { int lim = qi0 - 1089; if (lim > 0) u_start = ((lim + 63) >> 6) << 6; }

    // Q load (group 0)
    {
#pragma unroll
        for (int it = 0; it < 4; it++) {
            int cid = tid + it * 256;
            int r = cid >> 3, qq = cid & 7;
            const void* src = q + ((size_t)(b * 2048 + qi0 + r) << 10) + h * 64 + qq * 8;
            uint32_t dst = sbase + (uint32_t)((A_Q + r * AQS + qq * 8) * 2);
            cp_async16(dst, src);
        }
        cp_commit();
    }

    auto issue_kv = [&](int u0, int s) {
#pragma unroll
        for (int it = 0; it < 4; it++) {
            int cid = tid + it * 256;
            int t = cid >> 9, r = (cid >> 3) & 63, qq = cid & 7;
            const __half* bp = t ? v16 : k16;
            const void* src = bp + ((size_t)(b * 1024 + u0 + r) << 10) + h * 64 + qq * 8;
            uint32_t dst = sbase + (uint32_t)((A_KV + s * A_STAGE + t * A_TILE + r * AQS + qq * 8) * 2);
            cp_async16(dst, src);
        }
        cp_commit();
    };
    issue_kv(u_start, 0);

    float d[8][4];
#pragma unroll
    for (int nt = 0; nt < 8; nt++)
#pragma unroll
        for (int e = 0; e < 4; e++) d[nt][e] = 0.0f;
    float m0 = -1e30f, m1 = -1e30f, l0 = 0.0f, l1 = 0.0f;

    const int i0 = qi0 + w * 16 + (lane >> 2);
    const int i1 = i0 + 8;

    for (int u0 = u_start; u0 < 1024; u0 += 64) {
        const int st = ((u0 - u_start) >> 6) & 1;
        const bool more = (u0 + 64 < 1024);
        if (more) {
            issue_kv(u0 + 64, st ^ 1);
            asm volatile("cp.async.wait_group 1;" ::: "memory");
        } else {
            asm volatile("cp.async.wait_group 0;" ::: "memory");
        }
        __syncthreads();

        const uint32_t stg = sbase + (uint32_t)((A_KV + st * A_STAGE) * 2);

        // ---- S = Q * K ----
        float s_[8][4];
#pragma unroll
        for (int nt = 0; nt < 8; nt++)
#pragma unroll
            for (int e = 0; e < 4; e++) s_[nt][e] = 0.0f;

#pragma unroll
        for (int ks = 0; ks < 4; ks++) {
            uint32_t af[4];
            ldsm_x4(af[0], af[1], af[2], af[3],
                sbase + (uint32_t)(((w * 16 + (lane & 15)) * AQS + ks * 16 + (lane >> 4) * 8) * 2));
            const int mrow = lane >> 3;
            uint32_t bf[4][4];
#pragma unroll
            for (int g = 0; g < 4; g++)
                ldsm_x4(bf[g][0], bf[g][1], bf[g][2], bf[g][3],
                    stg + (uint32_t)(((g * 16 + (mrow & 2) * 4 + (lane & 7)) * AQS
                                      + ks * 16 + (mrow & 1) * 8) * 2));
#pragma unroll
            for (int nt = 0; nt < 8; nt++)
                mma_f16(s_[nt], af, bf[nt >> 1][(nt & 1) * 2], bf[nt >> 1][(nt & 1) * 2 + 1]);
        }

        // ---- online softmax ----
        float rmax0 = -1e30f, rmax1 = -1e30f;
#pragma unroll
        for (int nt = 0; nt < 8; nt++) {
            const int uc = u0 + nt * 8 + (lane & 3) * 2;
#pragma unroll
            for (int e = 0; e < 4; e++) {
                const int u = uc + (e & 1);
                const int i = (e < 2) ? i0 : i1;
                const int mf = (u >= i - 2) + (u >= i - 1026);
                if (mf == 0) s_[nt][e] = -1e30f;
                if (e < 2) rmax0 = fmaxf(rmax0, s_[nt][e]);
                else       rmax1 = fmaxf(rmax1, s_[nt][e]);
            }
        }
        rmax0 = fmaxf(rmax0, __shfl_xor_sync(0xffffffffu, rmax0, 1));
        rmax0 = fmaxf(rmax0, __shfl_xor_sync(0xffffffffu, rmax0, 2));
        rmax1 = fmaxf(rmax1, __shfl_xor_sync(0xffffffffu, rmax1, 1));
        rmax1 = fmaxf(rmax1, __shfl_xor_sync(0xffffffffu, rmax1, 2));
        const float mn0 = fmaxf(m0, rmax0), mn1 = fmaxf(m1, rmax1);
        const float sc0 = fexp2(m0 - mn0),  sc1 = fexp2(m1 - mn1);
        m0 = mn0; m1 = mn1;
        l0 *= sc0; l1 *= sc1;
#pragma unroll
        for (int nt = 0; nt < 8; nt++) {
            d[nt][0] *= sc0; d[nt][1] *= sc0; d[nt][2] *= sc1; d[nt][3] *= sc1;
            const int uc = u0 + nt * 8 + (lane & 3) * 2;
#pragma unroll
            for (int e = 0; e < 4; e++) {
                const int u = uc + (e & 1);
                const int i = (e < 2) ? i0 : i1;
                const float mf = (float)((u >= i - 2) + (u >= i - 1026));
                const float p = mf * fexp2(s_[nt][e] - ((e < 2) ? mn0 : mn1));
                s_[nt][e] = p;
                if (e < 2) l0 += p; else l1 += p;
            }
        }

        // ---- O += P * V ----
#pragma unroll
        for (int ks = 0; ks < 4; ks++) {
            uint32_t ph[4];
#pragma unroll
            for (int j = 0; j < 4; j++) {
                const int nt = 2 * ks + (j >> 1);
                __half2 H = __floats2half2_rn(s_[nt][(j & 1) * 2], s_[nt][(j & 1) * 2 + 1]);
                ph[j] = *reinterpret_cast<uint32_t*>(&H);
            }
            const uint32_t voff = (uint32_t)(((ks * 16 + ((lane >> 3) & 1) * 8 + (lane & 7)) * AQS) * 2)
                                + (uint32_t)((lane >> 4) * 16);
#pragma unroll
            for (int t = 0; t < 4; t++) {
                uint32_t vf[4];
                ldsm_x4_t(vf[0], vf[1], vf[2], vf[3],
                          stg + (uint32_t)(A_TILE * 2) + voff + (uint32_t)(t * 32));
                mma_f16(d[2 * t + 0], ph, vf[0], vf[1]);
                mma_f16(d[2 * t + 1], ph, vf[2], vf[3]);
            }
        }
        __syncthreads();
    }

    // ---- epilogue ----
    l0 += __shfl_xor_sync(0xffffffffu, l0, 1);
    l0 += __shfl_xor_sync(0xffffffffu, l0, 2);
    l1 += __shfl_xor_sync(0xffffffffu, l1, 1);
    l1 += __shfl_xor_sync(0xffffffffu, l1, 2);
    const float inv0 = 1.0f / l0, inv1 = 1.0f / l1;
    const size_t row0 = (size_t)(b * 2048 + qi0 + w * 16 + (lane >> 2));
#pragma unroll
    for (int nt = 0; nt < 8; nt++) {
        const int col = h * 64 + nt * 8 + (lane & 3) * 2;
        *(__half2*)(o + row0 * 1024 + col)       = __floats2half2_rn(d[nt][0] * inv0, d[nt][1] * inv0);
        *(__half2*)(o + (row0 + 8) * 1024 + col) = __floats2half2_rn(d[nt][2] * inv1, d[nt][3] * inv1);
    }
}

// ============================ launch ============================
extern "C" void kernel_launch(void* const* d_in, const int* in_sizes, int n_in,
                              void* d_out, int out_size) {
    const float* x  = (const float*)d_in[0];
    const float* xd = (const float*)d_in[1];
    const float* Wq = (const float*)d_in[2];
    const float* Wk = (const float*)d_in[3];
    const float* Wv = (const float*)d_in[4];
    const float* Wo = (const float*)d_in[5];
    const float* bo = (const float*)d_in[6];
    float* out = (float*)d_out;

    __half *x16, *d16, *q16, *k16, *v16, *ao, *wq, *wk, *wv, *wo;
    cudaGetSymbolAddress((void**)&x16, g_x16);  cudaGetSymbolAddress((void**)&d16, g_d16);
    cudaGetSymbolAddress((void**)&q16, g_q16);  cudaGetSymbolAddress((void**)&k16, g_k16);
    cudaGetSymbolAddress((void**)&v16, g_v16);  cudaGetSymbolAddress((void**)&ao,  g_ao);
    cudaGetSymbolAddress((void**)&wq,  g_wq);   cudaGetSymbolAddress((void**)&wk,  g_wk);
    cudaGetSymbolAddress((void**)&wv,  g_wv);   cudaGetSymbolAddress((void**)&wo,  g_wo);

    cudaFuncSetAttribute(gemm_qkv_kernel, cudaFuncAttributeMaxDynamicSharedMemorySize, G_SMEM);
    cudaFuncSetAttribute(gemm_o_kernel,   cudaFuncAttributeMaxDynamicSharedMemorySize, G_SMEM);
    cudaFuncSetAttribute(attn_mma_kernel, cudaFuncAttributeMaxDynamicSharedMemorySize, ATTN_SMEM);

    const float qscale = 0.125f * 1.44269504088896341f;

    cast_f16_kernel<<<4096, 256>>>(x,  x16, 4096 * 1024 / 4);
    cast_f16_kernel<<<2048, 256>>>(xd, d16, 2048 * 1024 / 4);
    wsplit_all_kernel<<<dim3(32, 32, 4), dim3(32, 8)>>>(Wq, Wk, Wv, Wo, wq, wk, wv, wo);

    gemm_qkv_kernel<<<dim3(8, 64), 256, G_SMEM>>>(x16, d16, wq, wk, wv, q16, k16, v16, qscale);

    attn_mma_kernel<<<dim3(16, 16, 2), 256, ATTN_SMEM>>>(q16, k16, v16, ao);

    gemm_o_kernel<<<dim3(8, 32), 256, G_SMEM>>>(ao, wo, out, bo);
}

// round 8
// speedup vs baseline: 6.8783x; 1.0957x over previous
#include <cuda_runtime.h>
#include <cuda_fp16.h>
#include <cstdint>

// ============================ scratch (allocation-free) ============================
__device__ __half g_x16[4096 * 1024];
__device__ __half g_d16[2048 * 1024];
__device__ __half g_q16[4096 * 1024];
__device__ __half g_k16[2048 * 1024];
__device__ __half g_v16[2048 * 1024];
__device__ __half g_ao [4096 * 1024];
__device__ __half g_wq [1024 * 1024];
__device__ __half g_wk [1024 * 1024];
__device__ __half g_wv [1024 * 1024];
__device__ __half g_wo [1024 * 1024];

// ============================ PTX helpers (arch-generic) ============================
__device__ __forceinline__ uint32_t smem_u32(const void* p) {
    uint32_t a;
    asm("{ .reg .u64 t; cvta.to.shared.u64 t, %1; cvt.u32.u64 %0, t; }" : "=r"(a) : "l"(p));
    return a;
}
__device__ __forceinline__ void ldsm_x4(uint32_t& r0, uint32_t& r1, uint32_t& r2, uint32_t& r3,
                                        uint32_t addr) {
    asm volatile("ldmatrix.sync.aligned.m8n8.x4.shared.b16 {%0,%1,%2,%3}, [%4];"
                 : "=r"(r0), "=r"(r1), "=r"(r2), "=r"(r3) : "r"(addr));
}
__device__ __forceinline__ void ldsm_x4_t(uint32_t& r0, uint32_t& r1, uint32_t& r2, uint32_t& r3,
                                          uint32_t addr) {
    asm volatile("ldmatrix.sync.aligned.m8n8.x4.trans.shared.b16 {%0,%1,%2,%3}, [%4];"
                 : "=r"(r0), "=r"(r1), "=r"(r2), "=r"(r3) : "r"(addr));
}
__device__ __forceinline__ void mma_f16(float* d, const uint32_t* a, uint32_t b0, uint32_t b1) {
    asm volatile("mma.sync.aligned.m16n8k16.row.col.f32.f16.f16.f32 "
                 "{%0,%1,%2,%3}, {%4,%5,%6,%7}, {%8,%9}, {%0,%1,%2,%3};"
                 : "+f"(d[0]), "+f"(d[1]), "+f"(d[2]), "+f"(d[3])
                 : "r"(a[0]), "r"(a[1]), "r"(a[2]), "r"(a[3]), "r"(b0), "r"(b1));
}
__device__ __forceinline__ void cp_async16(uint32_t dst, const void* src) {
    asm volatile("cp.async.cg.shared.global [%0], [%1], 16;" :: "r"(dst), "l"(src) : "memory");
}
__device__ __forceinline__ void cp_commit() {
    asm volatile("cp.async.commit_group;" ::: "memory");
}

__device__ __forceinline__ float fexp2(float x) {
    x = fmaxf(x, -120.0f);
    float t = x + 12582912.0f;
    float f = x - (t - 12582912.0f);
    int   e = __float_as_int(t) << 23;
    float p = 1.33335581e-3f;
    p = fmaf(p, f, 9.61812911e-3f);
    p = fmaf(p, f, 5.55041087e-2f);
    p = fmaf(p, f, 2.40226507e-1f);
    p = fmaf(p, f, 6.93147181e-1f);
    p = fmaf(p, f, 1.0f);
    return __int_as_float(__float_as_int(p) + e);
}

// ============================ conversions ============================
#define NX4 (4096 * 1024 / 4)
#define ND4 (2048 * 1024 / 4)
__global__ void cast_all_kernel(const float* __restrict__ x, const float* __restrict__ xd,
                                __half* __restrict__ x16, __half* __restrict__ d16) {
    int i = blockIdx.x * blockDim.x + threadIdx.x;
    const float* in; __half* out; int j;
    if (i < NX4)                { in = x;  out = x16; j = i; }
    else if (i < NX4 + ND4)     { in = xd; out = d16; j = i - NX4; }
    else return;
    float4 v = ((const float4*)in)[j];
    ((__half2*)out)[2 * j + 0] = __floats2half2_rn(v.x, v.y);
    ((__half2*)out)[2 * j + 1] = __floats2half2_rn(v.z, v.w);
}

// all 4 weights: [1024 k][1024 n] row-major -> [n][k] fp16, one launch (z selects)
__global__ void wsplit_all_kernel(const float* __restrict__ W0, const float* __restrict__ W1,
                                  const float* __restrict__ W2, const float* __restrict__ W3,
                                  __half* __restrict__ T0, __half* __restrict__ T1,
                                  __half* __restrict__ T2, __half* __restrict__ T3) {
    const int z = blockIdx.z;
    const float* W = (z == 0) ? W0 : (z == 1) ? W1 : (z == 2) ? W2 : W3;
    __half* T = (z == 0) ? T0 : (z == 1) ? T1 : (z == 2) ? T2 : T3;
    __shared__ float t[32][33];
    int x = blockIdx.x * 32 + threadIdx.x;
#pragma unroll
    for (int j = 0; j < 32; j += 8) {
        int kk = blockIdx.y * 32 + threadIdx.y + j;
        t[threadIdx.y + j][threadIdx.x] = W[kk * 1024 + x];
    }
    __syncthreads();
    int kx = blockIdx.y * 32 + threadIdx.x;
#pragma unroll
    for (int j = 0; j < 32; j += 8) {
        int n = blockIdx.x * 32 + threadIdx.y + j;
        T[n * 1024 + kx] = __float2half_rn(t[threadIdx.x][threadIdx.y + j]);
    }
}

// ============================ fp16 1-term GEMM core (3-stage, 1 sync/chunk) ===========
#define GTS      72
#define GTILE_B  (128 * GTS * 2)        // 18432
#define G_SMEM   (6 * GTILE_B)          // A,B x 3 stages = 110592

struct GemmCore {
    __device__ static void run(float d[2][8][4], const __half* A, const __half* B,
                               uint32_t sbase, int m0, int n0, int tid) {
        const int lane = tid & 31;
        const int wid  = tid >> 5;
        const int wm   = wid & 3;
        const int wn   = wid >> 2;

        auto issue_loads = [&](int c, int s) {
#pragma unroll
            for (int it = 0; it < 8; it++) {
                const int part = it >> 2;               // 0=A, 1=B
                const int w    = tid + (it & 3) * 256;
                const int row  = w >> 3;
                const int q    = w & 7;
                const __half* base = part ? B : A;
                const int grow = part ? (n0 + row) : (m0 + row);
                const void* src = base + ((size_t)grow << 10) + c * 64 + q * 8;
                uint32_t dst = sbase + (uint32_t)((s * 2 + part) * GTILE_B)
                             + (uint32_t)((row * GTS + q * 8) * 2);
                cp_async16(dst, src);
            }
            cp_commit();
        };

#pragma unroll
        for (int mt = 0; mt < 2; mt++)
#pragma unroll
            for (int nt = 0; nt < 8; nt++)
#pragma unroll
                for (int e = 0; e < 4; e++) d[mt][nt][e] = 0.0f;

        issue_loads(0, 0);
        issue_loads(1, 1);

        int ld_stage = 2, cur = 0;
        for (int c = 0; c < 16; c++) {
            asm volatile("cp.async.wait_group 1;" ::: "memory");
            __syncthreads();
            if (c + 2 < 16) issue_loads(c + 2, ld_stage);
            else            cp_commit();
            ld_stage = (ld_stage == 2) ? 0 : ld_stage + 1;

            const uint32_t stage = sbase + (uint32_t)(cur * 2 * GTILE_B);
            cur = (cur == 2) ? 0 : cur + 1;
            const uint32_t bbase = stage + (uint32_t)GTILE_B;
#pragma unroll
            for (int ks = 0; ks < 4; ks++) {
                const int k16 = ks * 16;
                uint32_t af[2][4];
#pragma unroll
                for (int mt = 0; mt < 2; mt++) {
                    uint32_t addr = stage +
                        (uint32_t)(((wm * 32 + mt * 16 + (lane & 15)) * GTS
                                    + k16 + ((lane >> 4) * 8)) * 2);
                    ldsm_x4(af[mt][0], af[mt][1], af[mt][2], af[mt][3], addr);
                }
                const int mrow = lane >> 3;
                uint32_t bf[4][4];
#pragma unroll
                for (int g = 0; g < 4; g++) {
                    uint32_t addr = bbase +
                        (uint32_t)(((wn * 64 + g * 16 + (mrow & 2) * 4 + (lane & 7)) * GTS
                                    + k16 + ((mrow & 1) * 8)) * 2);
                    ldsm_x4(bf[g][0], bf[g][1], bf[g][2], bf[g][3], addr);
                }
#pragma unroll
                for (int mt = 0; mt < 2; mt++)
#pragma unroll
                    for (int nt = 0; nt < 8; nt++)
                        mma_f16(d[mt][nt], af[mt],
                                bf[nt >> 1][(nt & 1) * 2], bf[nt >> 1][(nt & 1) * 2 + 1]);
            }
        }
    }
};

// merged q/k/v projection: grid (8, 64); by<32: q, by<48: k, else v. fp16 out.
__global__ __launch_bounds__(256, 2)
void gemm_qkv_kernel(const __half* __restrict__ x16, const __half* __restrict__ d16,
                     const __half* __restrict__ wq, const __half* __restrict__ wk,
                     const __half* __restrict__ wv,
                     __half* __restrict__ q16, __half* __restrict__ k16,
                     __half* __restrict__ v16, float qscale) {
    extern __shared__ char smem[];
    const uint32_t sbase = smem_u32(smem);
    const int tid = threadIdx.x;
    const int by  = blockIdx.y;

    const __half* A; const __half* B; __half* C; float alpha; int m0;
    if (by < 32)      { A = x16; B = wq; C = q16; alpha = qscale; m0 = by * 128; }
    else if (by < 48) { A = d16; B = wk; C = k16; alpha = 1.0f;   m0 = (by - 32) * 128; }
    else              { A = d16; B = wv; C = v16; alpha = 1.0f;   m0 = (by - 48) * 128; }
    const int n0 = blockIdx.x * 128;

    float d[2][8][4];
    GemmCore::run(d, A, B, sbase, m0, n0, tid);

    const int lane = tid & 31, wid = tid >> 5, wm = wid & 3, wn = wid >> 2;
#pragma unroll
    for (int mt = 0; mt < 2; mt++) {
        const int row0 = m0 + wm * 32 + mt * 16 + (lane >> 2);
#pragma unroll
        for (int nt = 0; nt < 8; nt++) {
            const int col = n0 + wn * 64 + nt * 8 + (lane & 3) * 2;
            *(__half2*)(C + (size_t)row0 * 1024 + col) =
                __floats2half2_rn(d[mt][nt][0] * alpha, d[mt][nt][1] * alpha);
            *(__half2*)(C + (size_t)(row0 + 8) * 1024 + col) =
                __floats2half2_rn(d[mt][nt][2] * alpha, d[mt][nt][3] * alpha);
        }
    }
}

// output projection: fp32 + bias
__global__ __launch_bounds__(256, 2)
void gemm_o_kernel(const __half* __restrict__ A, const __half* __restrict__ B,
                   float* __restrict__ Cf, const float* __restrict__ bias) {
    extern __shared__ char smem[];
    const uint32_t sbase = smem_u32(smem);
    const int tid = threadIdx.x;
    const int m0 = blockIdx.y * 128;
    const int n0 = blockIdx.x * 128;

    float d[2][8][4];
    GemmCore::run(d, A, B, sbase, m0, n0, tid);

    const int lane = tid & 31, wid = tid >> 5, wm = wid & 3, wn = wid >> 2;
#pragma unroll
    for (int mt = 0; mt < 2; mt++) {
        const int row0 = m0 + wm * 32 + mt * 16 + (lane >> 2);
#pragma unroll
        for (int nt = 0; nt < 8; nt++) {
            const int col = n0 + wn * 64 + nt * 8 + (lane & 3) * 2;
            const float bx = bias[col], by = bias[col + 1];
            *(float2*)(Cf + (size_t)row0 * 1024 + col) =
                make_float2(d[mt][nt][0] + bx, d[mt][nt][1] + by);
            *(float2*)(Cf + (size_t)(row0 + 8) * 1024 + col) =
                make_float2(d[mt][nt][2] + bx, d[mt][nt][3] + by);
        }
    }
}

// ============================ tensor-core banded attention ============================
// Q persistent; K + V double-buffered over 3 stages, 1 sync per key-block.
// Uniform-mask fast path: mf constant on non-boundary blocks; c=2 folds into exp2(+1).
#define AQS     72
#define A_Q     0                        // 128*72 = 9216 elems
#define A_KV    9216
#define A_TILE  4608                     // 64*72
#define A_STAGE (2 * A_TILE)             // K, V
#define ATTN_SMEM ((A_KV + 3 * A_STAGE) * 2)   // 73728 B

__global__ __launch_bounds__(256, 2)
void attn_mma_kernel(const __half* __restrict__ q,
                     const __half* __restrict__ k16,
                     const __half* __restrict__ v16,
                     __half* __restrict__ o) {
    extern __shared__ char smem[];
    const uint32_t sbase = smem_u32(smem);
    const int tid = threadIdx.x, lane = tid & 31, w = tid >> 5;
    const int qt = blockIdx.x, h = blockIdx.y, b = blockIdx.z;
    const int qi0 = qt * 128;

    int u_start = 0;
    { int lim = qi0 - 1089; if (lim > 0) u_start = ((lim + 63) >> 6) << 6; }

    // Q load (group 0)
    {
#pragma unroll
        for (int it = 0; it < 4; it++) {
            int cid = tid + it * 256;
            int r = cid >> 3, qq = cid & 7;
            const void* src = q + ((size_t)(b * 2048 + qi0 + r) << 10) + h * 64 + qq * 8;
            uint32_t dst = sbase + (uint32_t)((A_Q + r * AQS + qq * 8) * 2);
            cp_async16(dst, src);
        }
        cp_commit();
    }

    auto issue_kv = [&](int u0, int s) {
#pragma unroll
        for (int it = 0; it < 4; it++) {
            int cid = tid + it * 256;
            int t = cid >> 9, r = (cid >> 3) & 63, qq = cid & 7;
            const __half* bp = t ? v16 : k16;
            const void* src = bp + ((size_t)(b * 1024 + u0 + r) << 10) + h * 64 + qq * 8;
            uint32_t dst = sbase + (uint32_t)((A_KV + s * A_STAGE + t * A_TILE + r * AQS + qq * 8) * 2);
            cp_async16(dst, src);
        }
        cp_commit();
    };
    issue_kv(u_start, 0);            // >= 3 key blocks always remain, so +64 is valid
    issue_kv(u_start + 64, 1);

    float d[8][4];
#pragma unroll
    for (int nt = 0; nt < 8; nt++)
#pragma unroll
        for (int e = 0; e < 4; e++) d[nt][e] = 0.0f;
    float m0 = -1e30f, m1 = -1e30f, l0 = 0.0f, l1 = 0.0f;

    const int i0 = qi0 + w * 16 + (lane >> 2);
    const int i1 = i0 + 8;

    int ld_stage = 2, cur = 0;
    for (int u0 = u_start; u0 < 1024; u0 += 64) {
        asm volatile("cp.async.wait_group 1;" ::: "memory");
        __syncthreads();
        if (u0 + 128 < 1024) issue_kv(u0 + 128, ld_stage);
        else                 cp_commit();
        ld_stage = (ld_stage == 2) ? 0 : ld_stage + 1;

        const uint32_t stg = sbase + (uint32_t)((A_KV + cur * A_STAGE) * 2);
        cur = (cur == 2) ? 0 : cur + 1;

        // ---- S = Q * K ----
        float s_[8][4];
#pragma unroll
        for (int nt = 0; nt < 8; nt++)
#pragma unroll
            for (int e = 0; e < 4; e++) s_[nt][e] = 0.0f;

#pragma unroll
        for (int ks = 0; ks < 4; ks++) {
            uint32_t af[4];
            ldsm_x4(af[0], af[1], af[2], af[3],
                sbase + (uint32_t)(((w * 16 + (lane & 15)) * AQS + ks * 16 + (lane >> 4) * 8) * 2));
            const int mrow = lane >> 3;
            uint32_t bf[4][4];
#pragma unroll
            for (int g = 0; g < 4; g++)
                ldsm_x4(bf[g][0], bf[g][1], bf[g][2], bf[g][3],
                    stg + (uint32_t)(((g * 16 + (mrow & 2) * 4 + (lane & 7)) * AQS
                                      + ks * 16 + (mrow & 1) * 8) * 2));
#pragma unroll
            for (int nt = 0; nt < 8; nt++)
                mma_f16(s_[nt], af, bf[nt >> 1][(nt & 1) * 2], bf[nt >> 1][(nt & 1) * 2 + 1]);
        }

        // ---- online softmax ----
        // block-uniform mask classification
        const bool t1_all  = (u0 >= qi0 + 125);
        const bool t1_none = (u0 < qi0 - 65);
        const bool t2_all  = (u0 >= qi0 - 899);
        const bool uniform = (t1_all || t1_none) && t2_all;

        float rmax0 = -1e30f, rmax1 = -1e30f;
        if (uniform) {
#pragma unroll
            for (int nt = 0; nt < 8; nt++) {
                rmax0 = fmaxf(rmax0, fmaxf(s_[nt][0], s_[nt][1]));
                rmax1 = fmaxf(rmax1, fmaxf(s_[nt][2], s_[nt][3]));
            }
        } else {
#pragma unroll
            for (int nt = 0; nt < 8; nt++) {
                const int uc = u0 + nt * 8 + (lane & 3) * 2;
#pragma unroll
                for (int e = 0; e < 4; e++) {
                    const int u = uc + (e & 1);
                    const int i = (e < 2) ? i0 : i1;
                    const int mf = (u >= i - 2) + (u >= i - 1026);
                    if (mf == 0) s_[nt][e] = -1e30f;
                    if (e < 2) rmax0 = fmaxf(rmax0, s_[nt][e]);
                    else       rmax1 = fmaxf(rmax1, s_[nt][e]);
                }
            }
        }
        rmax0 = fmaxf(rmax0, __shfl_xor_sync(0xffffffffu, rmax0, 1));
        rmax0 = fmaxf(rmax0, __shfl_xor_sync(0xffffffffu, rmax0, 2));
        rmax1 = fmaxf(rmax1, __shfl_xor_sync(0xffffffffu, rmax1, 1));
        rmax1 = fmaxf(rmax1, __shfl_xor_sync(0xffffffffu, rmax1, 2));
        const float mn0 = fmaxf(m0, rmax0), mn1 = fmaxf(m1, rmax1);
        const float sc0 = fexp2(m0 - mn0),  sc1 = fexp2(m1 - mn1);
        m0 = mn0; m1 = mn1;
        l0 *= sc0; l1 *= sc1;
#pragma unroll
        for (int nt = 0; nt < 8; nt++) {
            d[nt][0] *= sc0; d[nt][1] *= sc0; d[nt][2] *= sc1; d[nt][3] *= sc1;
        }

        if (uniform) {
            const float bias = t1_all ? 1.0f : 0.0f;   // exp2(x+1) == 2*exp2(x): mf==2 folded
#pragma unroll
            for (int nt = 0; nt < 8; nt++) {
#pragma unroll
                for (int e = 0; e < 4; e++) {
                    const float p = fexp2(s_[nt][e] - ((e < 2) ? mn0 : mn1) + bias);
                    s_[nt][e] = p;
                    if (e < 2) l0 += p; else l1 += p;
                }
            }
        } else {
#pragma unroll
            for (int nt = 0; nt < 8; nt++) {
                const int uc = u0 + nt * 8 + (lane & 3) * 2;
#pragma unroll
                for (int e = 0; e < 4; e++) {
                    const int u = uc + (e & 1);
                    const int i = (e < 2) ? i0 : i1;
                    const float mf = (float)((u >= i - 2) + (u >= i - 1026));
                    const float p = mf * fexp2(s_[nt][e] - ((e < 2) ? mn0 : mn1));
                    s_[nt][e] = p;
                    if (e < 2) l0 += p; else l1 += p;
                }
            }
        }

        // ---- O += P * V ----
#pragma unroll
        for (int ks = 0; ks < 4; ks++) {
            uint32_t ph[4];
#pragma unroll
            for (int j = 0; j < 4; j++) {
                const int nt = 2 * ks + (j >> 1);
                __half2 H = __floats2half2_rn(s_[nt][(j & 1) * 2], s_[nt][(j & 1) * 2 + 1]);
                ph[j] = *reinterpret_cast<uint32_t*>(&H);
            }
            const uint32_t voff = (uint32_t)(((ks * 16 + ((lane >> 3) & 1) * 8 + (lane & 7)) * AQS) * 2)
                                + (uint32_t)((lane >> 4) * 16);
#pragma unroll
            for (int t = 0; t < 4; t++) {
                uint32_t vf[4];
                ldsm_x4_t(vf[0], vf[1], vf[2], vf[3],
                          stg + (uint32_t)(A_TILE * 2) + voff + (uint32_t)(t * 32));
                mma_f16(d[2 * t + 0], ph, vf[0], vf[1]);
                mma_f16(d[2 * t + 1], ph, vf[2], vf[3]);
            }
        }
    }

    // ---- epilogue ----
    l0 += __shfl_xor_sync(0xffffffffu, l0, 1);
    l0 += __shfl_xor_sync(0xffffffffu, l0, 2);
    l1 += __shfl_xor_sync(0xffffffffu, l1, 1);
    l1 += __shfl_xor_sync(0xffffffffu, l1, 2);
    const float inv0 = 1.0f / l0, inv1 = 1.0f / l1;
    const size_t row0 = (size_t)(b * 2048 + qi0 + w * 16 + (lane >> 2));
#pragma unroll
    for (int nt = 0; nt < 8; nt++) {
        const int col = h * 64 + nt * 8 + (lane & 3) * 2;
        *(__half2*)(o + row0 * 1024 + col)       = __floats2half2_rn(d[nt][0] * inv0, d[nt][1] * inv0);
        *(__half2*)(o + (row0 + 8) * 1024 + col) = __floats2half2_rn(d[nt][2] * inv1, d[nt][3] * inv1);
    }
}

// ============================ launch ============================
extern "C" void kernel_launch(void* const* d_in, const int* in_sizes, int n_in,
                              void* d_out, int out_size) {
    const float* x  = (const float*)d_in[0];
    const float* xd = (const float*)d_in[1];
    const float* Wq = (const float*)d_in[2];
    const float* Wk = (const float*)d_in[3];
    const float* Wv = (const float*)d_in[4];
    const float* Wo = (const float*)d_in[5];
    const float* bo = (const float*)d_in[6];
    float* out = (float*)d_out;

    __half *x16, *d16, *q16, *k16, *v16, *ao, *wq, *wk, *wv, *wo;
    cudaGetSymbolAddress((void**)&x16, g_x16);  cudaGetSymbolAddress((void**)&d16, g_d16);
    cudaGetSymbolAddress((void**)&q16, g_q16);  cudaGetSymbolAddress((void**)&k16, g_k16);
    cudaGetSymbolAddress((void**)&v16, g_v16);  cudaGetSymbolAddress((void**)&ao,  g_ao);
    cudaGetSymbolAddress((void**)&wq,  g_wq);   cudaGetSymbolAddress((void**)&wk,  g_wk);
    cudaGetSymbolAddress((void**)&wv,  g_wv);   cudaGetSymbolAddress((void**)&wo,  g_wo);

    cudaFuncSetAttribute(gemm_qkv_kernel, cudaFuncAttributeMaxDynamicSharedMemorySize, G_SMEM);
    cudaFuncSetAttribute(gemm_o_kernel,   cudaFuncAttributeMaxDynamicSharedMemorySize, G_SMEM);
    cudaFuncSetAttribute(attn_mma_kernel, cudaFuncAttributeMaxDynamicSharedMemorySize, ATTN_SMEM);

    const float qscale = 0.125f * 1.44269504088896341f;

    cast_all_kernel<<<(NX4 + ND4 + 255) / 256, 256>>>(x, xd, x16, d16);
    wsplit_all_kernel<<<dim3(32, 32, 4), dim3(32, 8)>>>(Wq, Wk, Wv, Wo, wq, wk, wv, wo);

    gemm_qkv_kernel<<<dim3(8, 64), 256, G_SMEM>>>(x16, d16, wq, wk, wv, q16, k16, v16, qscale);

    attn_mma_kernel<<<dim3(16, 16, 2), 256, ATTN_SMEM>>>(q16, k16, v16, ao);

    gemm_o_kernel<<<dim3(8, 32), 256, G_SMEM>>>(ao, wo, out, bo);
}

// round 9
// speedup vs baseline: 8.0191x; 1.1659x over previous
#include <cuda_runtime.h>
#include <cuda_fp16.h>
#include <cstdint>

// ============================ scratch (allocation-free) ============================
__device__ __half g_x16[4096 * 1024];
__device__ __half g_d16[2048 * 1024];
__device__ __half g_q16[4096 * 1024];
__device__ __half g_k16[2048 * 1024];
__device__ __half g_v16[2048 * 1024];
__device__ __half g_ao [4096 * 1024];
__device__ __half g_wq [1024 * 1024];
__device__ __half g_wk [1024 * 1024];
__device__ __half g_wv [1024 * 1024];
__device__ __half g_wo [1024 * 1024];

// ============================ PTX helpers (arch-generic) ============================
__device__ __forceinline__ uint32_t smem_u32(const void* p) {
    uint32_t a;
    asm("{ .reg .u64 t; cvta.to.shared.u64 t, %1; cvt.u32.u64 %0, t; }" : "=r"(a) : "l"(p));
    return a;
}
__device__ __forceinline__ void ldsm_x4(uint32_t& r0, uint32_t& r1, uint32_t& r2, uint32_t& r3,
                                        uint32_t addr) {
    asm volatile("ldmatrix.sync.aligned.m8n8.x4.shared.b16 {%0,%1,%2,%3}, [%4];"
                 : "=r"(r0), "=r"(r1), "=r"(r2), "=r"(r3) : "r"(addr));
}
__device__ __forceinline__ void ldsm_x4_t(uint32_t& r0, uint32_t& r1, uint32_t& r2, uint32_t& r3,
                                          uint32_t addr) {
    asm volatile("ldmatrix.sync.aligned.m8n8.x4.trans.shared.b16 {%0,%1,%2,%3}, [%4];"
                 : "=r"(r0), "=r"(r1), "=r"(r2), "=r"(r3) : "r"(addr));
}
__device__ __forceinline__ void mma_f16(float* d, const uint32_t* a, uint32_t b0, uint32_t b1) {
    asm volatile("mma.sync.aligned.m16n8k16.row.col.f32.f16.f16.f32 "
                 "{%0,%1,%2,%3}, {%4,%5,%6,%7}, {%8,%9}, {%0,%1,%2,%3};"
                 : "+f"(d[0]), "+f"(d[1]), "+f"(d[2]), "+f"(d[3])
                 : "r"(a[0]), "r"(a[1]), "r"(a[2]), "r"(a[3]), "r"(b0), "r"(b1));
}
__device__ __forceinline__ void cp_async16(uint32_t dst, const void* src) {
    asm volatile("cp.async.cg.shared.global [%0], [%1], 16;" :: "r"(dst), "l"(src) : "memory");
}
__device__ __forceinline__ void cp_commit() {
    asm volatile("cp.async.commit_group;" ::: "memory");
}

// ============================ conversions ============================
#define NX4 (4096 * 1024 / 4)
#define ND4 (2048 * 1024 / 4)
__global__ void cast_all_kernel(const float* __restrict__ x, const float* __restrict__ xd,
                                __half* __restrict__ x16, __half* __restrict__ d16) {
    int i = blockIdx.x * blockDim.x + threadIdx.x;
    const float* in; __half* out; int j;
    if (i < NX4)                { in = x;  out = x16; j = i; }
    else if (i < NX4 + ND4)     { in = xd; out = d16; j = i - NX4; }
    else return;
    float4 v = ((const float4*)in)[j];
    ((__half2*)out)[2 * j + 0] = __floats2half2_rn(v.x, v.y);
    ((__half2*)out)[2 * j + 1] = __floats2half2_rn(v.z, v.w);
}

// all 4 weights: [1024 k][1024 n] row-major -> [n][k] fp16, one launch (z selects)
__global__ void wsplit_all_kernel(const float* __restrict__ W0, const float* __restrict__ W1,
                                  const float* __restrict__ W2, const float* __restrict__ W3,
                                  __half* __restrict__ T0, __half* __restrict__ T1,
                                  __half* __restrict__ T2, __half* __restrict__ T3) {
    const int z = blockIdx.z;
    const float* W = (z == 0) ? W0 : (z == 1) ? W1 : (z == 2) ? W2 : W3;
    __half* T = (z == 0) ? T0 : (z == 1) ? T1 : (z == 2) ? T2 : T3;
    __shared__ float t[32][33];
    int x = blockIdx.x * 32 + threadIdx.x;
#pragma unroll
    for (int j = 0; j < 32; j += 8) {
        int kk = blockIdx.y * 32 + threadIdx.y + j;
        t[threadIdx.y + j][threadIdx.x] = W[kk * 1024 + x];
    }
    __syncthreads();
    int kx = blockIdx.y * 32 + threadIdx.x;
#pragma unroll
    for (int j = 0; j < 32; j += 8) {
        int n = blockIdx.x * 32 + threadIdx.y + j;
        T[n * 1024 + kx] = __float2half_rn(t[threadIdx.x][threadIdx.y + j]);
    }
}

// ============================ fp16 1-term GEMM core (3-stage, 1 sync/chunk) ===========
#define GTS      72
#define GTILE_B  (128 * GTS * 2)        // 18432
#define G_SMEM   (6 * GTILE_B)          // A,B x 3 stages = 110592

struct GemmCore {
    __device__ static void run(float d[2][8][4], const __half* A, const __half* B,
                               uint32_t sbase, int m0, int n0, int tid) {
        const int lane = tid & 31;
        const int wid  = tid >> 5;
        const int wm   = wid & 3;
        const int wn   = wid >> 2;

        auto issue_loads = [&](int c, int s) {
#pragma unroll
            for (int it = 0; it < 8; it++) {
                const int part = it >> 2;               // 0=A, 1=B
                const int w    = tid + (it & 3) * 256;
                const int row  = w >> 3;
                const int q    = w & 7;
                const __half* base = part ? B : A;
                const int grow = part ? (n0 + row) : (m0 + row);
                const void* src = base + ((size_t)grow << 10) + c * 64 + q * 8;
                uint32_t dst = sbase + (uint32_t)((s * 2 + part) * GTILE_B)
                             + (uint32_t)((row * GTS + q * 8) * 2);
                cp_async16(dst, src);
            }
            cp_commit();
        };

#pragma unroll
        for (int mt = 0; mt < 2; mt++)
#pragma unroll
            for (int nt = 0; nt < 8; nt++)
#pragma unroll
                for (int e = 0; e < 4; e++) d[mt][nt][e] = 0.0f;

        issue_loads(0, 0);
        issue_loads(1, 1);

        int ld_stage = 2, cur = 0;
        for (int c = 0; c < 16; c++) {
            asm volatile("cp.async.wait_group 1;" ::: "memory");
            __syncthreads();
            if (c + 2 < 16) issue_loads(c + 2, ld_stage);
            else            cp_commit();
            ld_stage = (ld_stage == 2) ? 0 : ld_stage + 1;

            const uint32_t stage = sbase + (uint32_t)(cur * 2 * GTILE_B);
            cur = (cur == 2) ? 0 : cur + 1;
            const uint32_t bbase = stage + (uint32_t)GTILE_B;
#pragma unroll
            for (int ks = 0; ks < 4; ks++) {
                const int k16 = ks * 16;
                uint32_t af[2][4];
#pragma unroll
                for (int mt = 0; mt < 2; mt++) {
                    uint32_t addr = stage +
                        (uint32_t)(((wm * 32 + mt * 16 + (lane & 15)) * GTS
                                    + k16 + ((lane >> 4) * 8)) * 2);
                    ldsm_x4(af[mt][0], af[mt][1], af[mt][2], af[mt][3], addr);
                }
                const int mrow = lane >> 3;
                uint32_t bf[4][4];
#pragma unroll
                for (int g = 0; g < 4; g++) {
                    uint32_t addr = bbase +
                        (uint32_t)(((wn * 64 + g * 16 + (mrow & 2) * 4 + (lane & 7)) * GTS
                                    + k16 + ((mrow & 1) * 8)) * 2);
                    ldsm_x4(bf[g][0], bf[g][1], bf[g][2], bf[g][3], addr);
                }
#pragma unroll
                for (int mt = 0; mt < 2; mt++)
#pragma unroll
                    for (int nt = 0; nt < 8; nt++)
                        mma_f16(d[mt][nt], af[mt],
                                bf[nt >> 1][(nt & 1) * 2], bf[nt >> 1][(nt & 1) * 2 + 1]);
            }
        }
    }
};

// merged q/k/v projection: grid (8, 64); by<32: q, by<48: k, else v. fp16 out.
__global__ __launch_bounds__(256, 2)
void gemm_qkv_kernel(const __half* __restrict__ x16, const __half* __restrict__ d16,
                     const __half* __restrict__ wq, const __half* __restrict__ wk,
                     const __half* __restrict__ wv,
                     __half* __restrict__ q16, __half* __restrict__ k16,
                     __half* __restrict__ v16, float qscale) {
    extern __shared__ char smem[];
    const uint32_t sbase = smem_u32(smem);
    const int tid = threadIdx.x;
    const int by  = blockIdx.y;

    const __half* A; const __half* B; __half* C; float alpha; int m0;
    if (by < 32)      { A = x16; B = wq; C = q16; alpha = qscale; m0 = by * 128; }
    else if (by < 48) { A = d16; B = wk; C = k16; alpha = 1.0f;   m0 = (by - 32) * 128; }
    else              { A = d16; B = wv; C = v16; alpha = 1.0f;   m0 = (by - 48) * 128; }
    const int n0 = blockIdx.x * 128;

    float d[2][8][4];
    GemmCore::run(d, A, B, sbase, m0, n0, tid);

    const int lane = tid & 31, wid = tid >> 5, wm = wid & 3, wn = wid >> 2;
#pragma unroll
    for (int mt = 0; mt < 2; mt++) {
        const int row0 = m0 + wm * 32 + mt * 16 + (lane >> 2);
#pragma unroll
        for (int nt = 0; nt < 8; nt++) {
            const int col = n0 + wn * 64 + nt * 8 + (lane & 3) * 2;
            *(__half2*)(C + (size_t)row0 * 1024 + col) =
                __floats2half2_rn(d[mt][nt][0] * alpha, d[mt][nt][1] * alpha);
            *(__half2*)(C + (size_t)(row0 + 8) * 1024 + col) =
                __floats2half2_rn(d[mt][nt][2] * alpha, d[mt][nt][3] * alpha);
        }
    }
}

// output projection: fp32 + bias
__global__ __launch_bounds__(256, 2)
void gemm_o_kernel(const __half* __restrict__ A, const __half* __restrict__ B,
                   float* __restrict__ Cf, const float* __restrict__ bias) {
    extern __shared__ char smem[];
    const uint32_t sbase = smem_u32(smem);
    const int tid = threadIdx.x;
    const int m0 = blockIdx.y * 128;
    const int n0 = blockIdx.x * 128;

    float d[2][8][4];
    GemmCore::run(d, A, B, sbase, m0, n0, tid);

    const int lane = tid & 31, wid = tid >> 5, wm = wid & 3, wn = wid >> 2;
#pragma unroll
    for (int mt = 0; mt < 2; mt++) {
        const int row0 = m0 + wm * 32 + mt * 16 + (lane >> 2);
#pragma unroll
        for (int nt = 0; nt < 8; nt++) {
            const int col = n0 + wn * 64 + nt * 8 + (lane & 3) * 2;
            const float bx = bias[col], by = bias[col + 1];
            *(float2*)(Cf + (size_t)row0 * 1024 + col) =
                make_float2(d[mt][nt][0] + bx, d[mt][nt][1] + by);
            *(float2*)(Cf + (size_t)(row0 + 8) * 1024 + col) =
                make_float2(d[mt][nt][2] + bx, d[mt][nt][3] + by);
        }
    }
}

// ============================ tensor-core banded attention ============================
// No-max softmax: p = exp2(s) via ex2.approx.f16x2 (common bias cancels in p/sum(p)).
// Row-sum l via MMA against an all-ones B fragment (constant registers, no smem).
#define AQS     72
#define A_Q     0                        // 128*72 = 9216 elems
#define A_KV    9216
#define A_TILE  4608                     // 64*72
#define A_STAGE (2 * A_TILE)             // K, V
#define ATTN_SMEM ((A_KV + 3 * A_STAGE) * 2)   // 73728 B

__global__ __launch_bounds__(256, 2)
void attn_mma_kernel(const __half* __restrict__ q,
                     const __half* __restrict__ k16,
                     const __half* __restrict__ v16,
                     __half* __restrict__ o) {
    extern __shared__ char smem[];
    const uint32_t sbase = smem_u32(smem);
    const int tid = threadIdx.x, lane = tid & 31, w = tid >> 5;
    const int qt = blockIdx.x, h = blockIdx.y, b = blockIdx.z;
    const int qi0 = qt * 128;

    int u_start = 0;
    { int lim = qi0 - 1089; if (lim > 0) u_start = ((lim + 63) >> 6) << 6; }

    // Q load (group 0)
    {
#pragma unroll
        for (int it = 0; it < 4; it++) {
            int cid = tid + it * 256;
            int r = cid >> 3, qq = cid & 7;
            const void* src = q + ((size_t)(b * 2048 + qi0 + r) << 10) + h * 64 + qq * 8;
            uint32_t dst = sbase + (uint32_t)((A_Q + r * AQS + qq * 8) * 2);
            cp_async16(dst, src);
        }
        cp_commit();
    }

    auto issue_kv = [&](int u0, int s) {
#pragma unroll
        for (int it = 0; it < 4; it++) {
            int cid = tid + it * 256;
            int t = cid >> 9, r = (cid >> 3) & 63, qq = cid & 7;
            const __half* bp = t ? v16 : k16;
            const void* src = bp + ((size_t)(b * 1024 + u0 + r) << 10) + h * 64 + qq * 8;
            uint32_t dst = sbase + (uint32_t)((A_KV + s * A_STAGE + t * A_TILE + r * AQS + qq * 8) * 2);
            cp_async16(dst, src);
        }
        cp_commit();
    };
    issue_kv(u_start, 0);
    issue_kv(u_start + 64, 1);

    float d[8][4];
#pragma unroll
    for (int nt = 0; nt < 8; nt++)
#pragma unroll
        for (int e = 0; e < 4; e++) d[nt][e] = 0.0f;
    float dl[4] = {0.0f, 0.0f, 0.0f, 0.0f};   // row-sum accumulator (P @ ones)

    const int i0 = qi0 + w * 16 + (lane >> 2);
    const int i1 = i0 + 8;
    const uint32_t ONES2 = 0x3C003C00u;        // half2(1, 1)

    int ld_stage = 2, cur = 0;
    for (int u0 = u_start; u0 < 1024; u0 += 64) {
        asm volatile("cp.async.wait_group 1;" ::: "memory");
        __syncthreads();
        if (u0 + 128 < 1024) issue_kv(u0 + 128, ld_stage);
        else                 cp_commit();
        ld_stage = (ld_stage == 2) ? 0 : ld_stage + 1;

        const uint32_t stg = sbase + (uint32_t)((A_KV + cur * A_STAGE) * 2);
        cur = (cur == 2) ? 0 : cur + 1;

        // ---- S = Q * K ----
        float s_[8][4];
#pragma unroll
        for (int nt = 0; nt < 8; nt++)
#pragma unroll
            for (int e = 0; e < 4; e++) s_[nt][e] = 0.0f;

#pragma unroll
        for (int ks = 0; ks < 4; ks++) {
            uint32_t af[4];
            ldsm_x4(af[0], af[1], af[2], af[3],
                sbase + (uint32_t)(((w * 16 + (lane & 15)) * AQS + ks * 16 + (lane >> 4) * 8) * 2));
            const int mrow = lane >> 3;
            uint32_t bf[4][4];
#pragma unroll
            for (int g = 0; g < 4; g++)
                ldsm_x4(bf[g][0], bf[g][1], bf[g][2], bf[g][3],
                    stg + (uint32_t)(((g * 16 + (mrow & 2) * 4 + (lane & 7)) * AQS
                                      + ks * 16 + (mrow & 1) * 8) * 2));
#pragma unroll
            for (int nt = 0; nt < 8; nt++)
                mma_f16(s_[nt], af, bf[nt >> 1][(nt & 1) * 2], bf[nt >> 1][(nt & 1) * 2 + 1]);
        }

        // ---- p = exp2(s) packed to half2 (no running max; bias folds mf) ----
        const bool t1_all  = (u0 >= qi0 + 125);
        const bool t1_none = (u0 < qi0 - 65);
        const bool t2_all  = (u0 >= qi0 - 899);
        const bool uniform = (t1_all || t1_none) && t2_all;

        uint32_t ph2[8][2];
        if (uniform) {
            const __half2 bias2 = __float2half2_rn(t1_all ? 1.0f : 0.0f);  // exp2(s+1)=2*exp2(s)
#pragma unroll
            for (int nt = 0; nt < 8; nt++) {
                __half2 a0 = h2exp2(__hadd2(__floats2half2_rn(s_[nt][0], s_[nt][1]), bias2));
                __half2 a1 = h2exp2(__hadd2(__floats2half2_rn(s_[nt][2], s_[nt][3]), bias2));
                ph2[nt][0] = *reinterpret_cast<uint32_t*>(&a0);
                ph2[nt][1] = *reinterpret_cast<uint32_t*>(&a1);
            }
        } else {
#pragma unroll
            for (int nt = 0; nt < 8; nt++) {
                const int uc = u0 + nt * 8 + (lane & 3) * 2;
                float sv[4];
#pragma unroll
                for (int e = 0; e < 4; e++) {
                    const int u = uc + (e & 1);
                    const int i = (e < 2) ? i0 : i1;
                    const int mf = (u >= i - 2) + (u >= i - 1026);
                    sv[e] = (mf == 0) ? -1000.0f : s_[nt][e] + (mf == 2 ? 1.0f : 0.0f);
                }
                __half2 a0 = h2exp2(__floats2half2_rn(sv[0], sv[1]));
                __half2 a1 = h2exp2(__floats2half2_rn(sv[2], sv[3]));
                ph2[nt][0] = *reinterpret_cast<uint32_t*>(&a0);
                ph2[nt][1] = *reinterpret_cast<uint32_t*>(&a1);
            }
        }

        // ---- O += P * V ; l += P * ones ----
#pragma unroll
        for (int ks = 0; ks < 4; ks++) {
            uint32_t ph[4];
            ph[0] = ph2[2 * ks][0];
            ph[1] = ph2[2 * ks][1];
            ph[2] = ph2[2 * ks + 1][0];
            ph[3] = ph2[2 * ks + 1][1];
            mma_f16(dl, ph, ONES2, ONES2);   // row sums

            const uint32_t voff = (uint32_t)(((ks * 16 + ((lane >> 3) & 1) * 8 + (lane & 7)) * AQS) * 2)
                                + (uint32_t)((lane >> 4) * 16);
#pragma unroll
            for (int t = 0; t < 4; t++) {
                uint32_t vf[4];
                ldsm_x4_t(vf[0], vf[1], vf[2], vf[3],
                          stg + (uint32_t)(A_TILE * 2) + voff + (uint32_t)(t * 32));
                mma_f16(d[2 * t + 0], ph, vf[0], vf[1]);
                mma_f16(d[2 * t + 1], ph, vf[2], vf[3]);
            }
        }
    }

    // ---- epilogue: l comes straight from the ones-MMA (no shuffles) ----
    const float inv0 = 1.0f / dl[0], inv1 = 1.0f / dl[2];
    const size_t row0 = (size_t)(b * 2048 + qi0 + w * 16 + (lane >> 2));
#pragma unroll
    for (int nt = 0; nt < 8; nt++) {
        const int col = h * 64 + nt * 8 + (lane & 3) * 2;
        *(__half2*)(o + row0 * 1024 + col)       = __floats2half2_rn(d[nt][0] * inv0, d[nt][1] * inv0);
        *(__half2*)(o + (row0 + 8) * 1024 + col) = __floats2half2_rn(d[nt][2] * inv1, d[nt][3] * inv1);
    }
}

// ============================ launch ============================
extern "C" void kernel_launch(void* const* d_in, const int* in_sizes, int n_in,
                              void* d_out, int out_size) {
    const float* x  = (const float*)d_in[0];
    const float* xd = (const float*)d_in[1];
    const float* Wq = (const float*)d_in[2];
    const float* Wk = (const float*)d_in[3];
    const float* Wv = (const float*)d_in[4];
    const float* Wo = (const float*)d_in[5];
    const float* bo = (const float*)d_in[6];
    float* out = (float*)d_out;

    __half *x16, *d16, *q16, *k16, *v16, *ao, *wq, *wk, *wv, *wo;
    cudaGetSymbolAddress((void**)&x16, g_x16);  cudaGetSymbolAddress((void**)&d16, g_d16);
    cudaGetSymbolAddress((void**)&q16, g_q16);  cudaGetSymbolAddress((void**)&k16, g_k16);
    cudaGetSymbolAddress((void**)&v16, g_v16);  cudaGetSymbolAddress((void**)&ao,  g_ao);
    cudaGetSymbolAddress((void**)&wq,  g_wq);   cudaGetSymbolAddress((void**)&wk,  g_wk);
    cudaGetSymbolAddress((void**)&wv,  g_wv);   cudaGetSymbolAddress((void**)&wo,  g_wo);

    cudaFuncSetAttribute(gemm_qkv_kernel, cudaFuncAttributeMaxDynamicSharedMemorySize, G_SMEM);
    cudaFuncSetAttribute(gemm_o_kernel,   cudaFuncAttributeMaxDynamicSharedMemorySize, G_SMEM);
    cudaFuncSetAttribute(attn_mma_kernel, cudaFuncAttributeMaxDynamicSharedMemorySize, ATTN_SMEM);

    const float qscale = 0.125f * 1.44269504088896341f;

    cast_all_kernel<<<(NX4 + ND4 + 255) / 256, 256>>>(x, xd, x16, d16);
    wsplit_all_kernel<<<dim3(32, 32, 4), dim3(32, 8)>>>(Wq, Wk, Wv, Wo, wq, wk, wv, wo);

    gemm_qkv_kernel<<<dim3(8, 64), 256, G_SMEM>>>(x16, d16, wq, wk, wv, q16, k16, v16, qscale);

    attn_mma_kernel<<<dim3(16, 16, 2), 256, ATTN_SMEM>>>(q16, k16, v16, ao);

    gemm_o_kernel<<<dim3(8, 32), 256, G_SMEM>>>(ao, wo, out, bo);
}